// round 5
// baseline (speedup 1.0000x reference)
#include <cuda_runtime.h>
#include <math.h>

#define BATCH_MAX 65536
#define FEAT 584
#define FEAT_PAD 592

typedef unsigned long long u64t;

__device__ float g_feats[(size_t)BATCH_MAX * FEAT_PAD]; // conv features + quantum (+8 zero pad)

// Transposed weight copies (lane-coalesced layouts)
__device__ float g_w1t[27 * 16];     // [tap][co]
__device__ float g_w2t[144 * 32];    // [ci*9+tap][co]
__device__ float g_w3t[288 * 64];    // [ci*9+tap][co]

// ---- packed f32x2 helpers -------------------------------------------------
__device__ __forceinline__ float2 ffma2(float2 a, float2 b, float2 c) {
    u64t ua = *(u64t*)&a, ub = *(u64t*)&b, uc = *(u64t*)&c, ud;
    asm("fma.rn.f32x2 %0, %1, %2, %3;" : "=l"(ud) : "l"(ua), "l"(ub), "l"(uc));
    return *(float2*)&ud;
}
__device__ __forceinline__ float2 bcast2(float w) { return make_float2(w, w); }
__device__ __forceinline__ float2 fmax2(float2 a, float2 b) {
    return make_float2(fmaxf(a.x, b.x), fmaxf(a.y, b.y));
}
__device__ __forceinline__ unsigned f2tf32(float v) {
    unsigned o; asm("cvt.rna.tf32.f32 %0, %1;" : "=r"(o) : "f"(v)); return o;
}

// ---------------------------------------------------------------------------
// Kernel 0: transpose conv weights into lane-coalesced layouts.
// ---------------------------------------------------------------------------
__global__ void k_wt(const float* __restrict__ w1,
                     const float* __restrict__ w2,
                     const float* __restrict__ w3)
{
    const int i = blockIdx.x * 256 + threadIdx.x;
    if (i < 432)   { int co = i / 27,  r = i - co * 27;  g_w1t[r * 16 + co] = w1[i]; }
    if (i < 4608)  { int co = i / 144, r = i - co * 144; g_w2t[r * 32 + co] = w2[i]; }
    if (i < 18432) { int co = i / 288, r = i - co * 288; g_w3t[r * 64 + co] = w3[i]; }
}

// ---------------------------------------------------------------------------
// conv2 x-half (unchanged)
// ---------------------------------------------------------------------------
template<int C0, int WIN, int WOUT>
__device__ __forceinline__ void conv2_part(
    const float2* __restrict__ h1p, float2 bias, int lane, float2* __restrict__ pp)
{
    float2 acc[6][WOUT];
    #pragma unroll
    for (int y = 0; y < 6; y++)
        #pragma unroll
        for (int x = 0; x < WOUT; x++) acc[y][x] = bias;

    for (int ci = 0; ci < 16; ci++) {
        float2 w[9];
        #pragma unroll
        for (int i = 0; i < 9; i++) w[i] = bcast2(__ldg(g_w2t + (ci * 9 + i) * 32 + lane));
        const float2* hr = h1p + ci * 64;
        float2 r[3][WIN];
        #pragma unroll
        for (int j = 0; j < WIN; j++) { r[0][j] = hr[C0 + j]; r[1][j] = hr[8 + C0 + j]; }
        #pragma unroll
        for (int y = 0; y < 6; y++) {
            #pragma unroll
            for (int j = 0; j < WIN; j++) r[(y + 2) % 3][j] = hr[(y + 2) * 8 + C0 + j];
            #pragma unroll
            for (int x = 0; x < WOUT; x++) {
                float2 a = acc[y][x];
                a = ffma2(r[(y + 0) % 3][x + 0], w[0], a);
                a = ffma2(r[(y + 0) % 3][x + 1], w[1], a);
                a = ffma2(r[(y + 0) % 3][x + 2], w[2], a);
                a = ffma2(r[(y + 1) % 3][x + 0], w[3], a);
                a = ffma2(r[(y + 1) % 3][x + 1], w[4], a);
                a = ffma2(r[(y + 1) % 3][x + 2], w[5], a);
                a = ffma2(r[(y + 2) % 3][x + 0], w[6], a);
                a = ffma2(r[(y + 2) % 3][x + 1], w[7], a);
                a = ffma2(r[(y + 2) % 3][x + 2], w[8], a);
                acc[y][x] = a;
            }
        }
    }
    #pragma unroll
    for (int py = 0; py < 3; py++)
        #pragma unroll
        for (int pxl = 0; pxl < WOUT / 2; pxl++) {
            float2 m = fmax2(fmax2(acc[2 * py][2 * pxl], acc[2 * py][2 * pxl + 1]),
                             fmax2(acc[2 * py + 1][2 * pxl], acc[2 * py + 1][2 * pxl + 1]));
            m = fmax2(m, make_float2(0.f, 0.f));
            const int px = C0 / 2 + pxl;
            pp[lane * 25 + (py + 1) * 5 + (px + 1)] = m;
        }
}

// ---------------------------------------------------------------------------
// Kernel 1: conv pipeline + quantum sim (row stride FEAT_PAD; zero the pad)
// ---------------------------------------------------------------------------
__global__ __launch_bounds__(128) void k_conv(
    const float* __restrict__ board,
    const float* __restrict__ b1,
    const float* __restrict__ b2,
    const float* __restrict__ b3,
    const float* __restrict__ qp, int nsamp)
{
    extern __shared__ float2 smc[];
    const int warp = threadIdx.x >> 5;
    const int lane = threadIdx.x & 31;
    const int pidx = blockIdx.x * 4 + warp;
    const int s0 = 2 * pidx;
    if (s0 >= nsamp) return;
    const bool has2 = (s0 + 1 < nsamp);

    float2* inp = smc + (size_t)warp * 2016;
    float2* h1p = inp + 192;
    float2* pp  = inp + 1216;

    const float* bs0 = board + (size_t)s0 * 108;
    const float* bs1 = has2 ? bs0 + 108 : bs0;

    #pragma unroll
    for (int i = lane; i < 2016; i += 32) inp[i] = make_float2(0.f, 0.f);
    __syncwarp();

    for (int i = lane; i < 108; i += 32) {
        int ci = i / 36, r = i - ci * 36;
        int y = r / 6, x = r - y * 6;
        inp[ci * 64 + (y + 1) * 8 + (x + 1)] = make_float2(bs0[i], bs1[i]);
    }

    // quantum sim + zero the 8-float pad (cols 584..591)
    if (lane < 16) {
        const int smp = lane >> 3, qb = lane & 7;
        const int sg = s0 + smp;
        if (sg < nsamp) {
            const float* bq = board + (size_t)sg * 108;
            float xv = bq[qb], xn = bq[(qb + 1) & 7];
            float q = 0.f;
            #pragma unroll
            for (int l = 0; l < 3; l++) {
                float r0 = __ldg(qp + (l * 8 + qb) * 3 + 0);
                float r1 = __ldg(qp + (l * 8 + qb) * 3 + 1);
                float r2 = __ldg(qp + (l * 8 + qb) * 3 + 2);
                q = sinf(r0 * xv) * cosf(r1 * xn) + tanhf(r2 * q);
            }
            g_feats[(size_t)sg * FEAT_PAD + 576 + qb] = q;
            g_feats[(size_t)sg * FEAT_PAD + 584 + qb] = 0.f;   // pad: keep tf32 GEMM NaN-free
        }
    }
    __syncwarp();

    {
        const int co = lane & 15, half = lane >> 4;
        float2 w[27];
        #pragma unroll
        for (int i = 0; i < 27; i++) w[i] = bcast2(__ldg(g_w1t + i * 16 + co));
        const float2 bias = bcast2(__ldg(b1 + co));
        #pragma unroll
        for (int p = 0; p < 18; p++) {
            const int yy = half * 3 + p / 6;
            const int xx = p % 6;
            const int y8 = yy * 8;
            float2 a = bias;
            #pragma unroll
            for (int ci = 0; ci < 3; ci++)
                #pragma unroll
                for (int ky = 0; ky < 3; ky++)
                    #pragma unroll
                    for (int kx = 0; kx < 3; kx++)
                        a = ffma2(inp[ci * 64 + y8 + ky * 8 + xx + kx],
                                  w[ci * 9 + ky * 3 + kx], a);
            h1p[co * 64 + y8 + 8 + xx + 1] = fmax2(a, make_float2(0.f, 0.f));
        }
    }
    __syncwarp();

    {
        const float2 bias2 = bcast2(__ldg(b2 + lane));
        conv2_part<0, 6, 4>(h1p, bias2, lane, pp);
        conv2_part<4, 4, 2>(h1p, bias2, lane, pp);
    }
    __syncwarp();

    {
        float2 acc0[9], acc1[9];
        const float2 bz0 = bcast2(__ldg(b3 + lane));
        const float2 bz1 = bcast2(__ldg(b3 + lane + 32));
        #pragma unroll
        for (int i = 0; i < 9; i++) { acc0[i] = bz0; acc1[i] = bz1; }

        for (int ci = 0; ci < 32; ci++) {
            float2 wa[9], wb[9];
            #pragma unroll
            for (int i = 0; i < 9; i++) {
                wa[i] = bcast2(__ldg(g_w3t + (ci * 9 + i) * 64 + lane));
                wb[i] = bcast2(__ldg(g_w3t + (ci * 9 + i) * 64 + lane + 32));
            }
            const float2* ps = pp + ci * 25;
            float2 r[3][5];
            #pragma unroll
            for (int j = 0; j < 5; j++) { r[0][j] = ps[j]; r[1][j] = ps[5 + j]; }
            #pragma unroll
            for (int y = 0; y < 3; y++) {
                #pragma unroll
                for (int j = 0; j < 5; j++) r[(y + 2) % 3][j] = ps[(y + 2) * 5 + j];
                #pragma unroll
                for (int x = 0; x < 3; x++) {
                    float2 a0 = acc0[y * 3 + x], a1 = acc1[y * 3 + x];
                    #pragma unroll
                    for (int ky = 0; ky < 3; ky++)
                        #pragma unroll
                        for (int kx = 0; kx < 3; kx++) {
                            const float2 v = r[(y + ky) % 3][x + kx];
                            a0 = ffma2(v, wa[ky * 3 + kx], a0);
                            a1 = ffma2(v, wb[ky * 3 + kx], a1);
                        }
                    acc0[y * 3 + x] = a0; acc1[y * 3 + x] = a1;
                }
            }
        }
        float* f0 = g_feats + (size_t)s0 * FEAT_PAD;
        float* f1 = f0 + FEAT_PAD;
        #pragma unroll
        for (int i = 0; i < 9; i++) {
            float2 v0 = fmax2(acc0[i], make_float2(0.f, 0.f));
            float2 v1 = fmax2(acc1[i], make_float2(0.f, 0.f));
            f0[lane * 9 + i] = v0.x;
            f0[(lane + 32) * 9 + i] = v1.x;
            if (has2) { f1[lane * 9 + i] = v0.y; f1[(lane + 32) * 9 + i] = v1.y; }
        }
    }
}

// ---------------------------------------------------------------------------
// Kernel 2 (fused, tf32 tensor-core): C1 = relu(feats @ [pt_w1|cf_w1] + b),
// then both heads. BM=128, N=192, K=584 (pad->592), BK=16, mma.m16n8k8 tf32.
// 8 warps: warp-tile 32(M) x 96(N). Fragment-major smem operands.
// ---------------------------------------------------------------------------
#define FC1_SMEM (33728 * 4)

__global__ __launch_bounds__(256) void k_fc1(
    const float* __restrict__ ptw1, const float* __restrict__ ptb1,
    const float* __restrict__ cfw1, const float* __restrict__ cfb1,
    const float* __restrict__ ptw2, const float* __restrict__ ptb2,
    const float* __restrict__ ptw3, const float* __restrict__ ptb3,
    const float* __restrict__ cfw2, const float* __restrict__ cfb2,
    float* __restrict__ out)
{
    extern __shared__ float sfc[];
    unsigned* A_s = (unsigned*)sfc;            // 2048
    unsigned* B_s = (unsigned*)(sfc + 2048);   // 3072
    float* C1s    = sfc;                       // 25088 (post-GEMM alias)
    float* W2s    = sfc + 25088;               // 8192
    float* BiasS  = sfc + 33280;               // 192
    float* W3s    = sfc + 33472;               // 128
    float* CW2s   = sfc + 33600;               // 64
    float* B2s    = sfc + 33664;               // 64

    const int t = threadIdx.x;
    const int m0 = blockIdx.x * 128;
    const int warp = t >> 5, lane = t & 31;
    const int wm = warp >> 1, wn = warp & 1;
    const int g = lane >> 2, tg = lane & 3;

    // preload head weights / biases (regions disjoint from GEMM buffers)
    for (int i = t; i < 8192; i += 256) W2s[i] = __ldg(ptw2 + i);
    if (t < 192) BiasS[t] = (t < 128) ? __ldg(ptb1 + t) : __ldg(cfb1 + t - 128);
    if (t < 128) W3s[t] = __ldg(ptw3 + t);
    if (t < 64)  { CW2s[t] = __ldg(cfw2 + t); B2s[t] = __ldg(ptb2 + t); }

    float acc[2][12][4];
    #pragma unroll
    for (int i = 0; i < 2; i++)
        #pragma unroll
        for (int j = 0; j < 12; j++)
            #pragma unroll
            for (int r = 0; r < 4; r++) acc[i][j][r] = 0.f;

    // A-loader mapping: thread -> row am, 8-col chunk at (t&1)*8
    const int am = t >> 1;
    const int kcA = t & 1;                 // which k8 chunk within BK=16
    const int rA = am & 15, mtA = am >> 4;
    const int baseA = ((kcA * 8 + mtA) * 32 + (rA & 7) * 4) * 4 + (rA >> 3);
    const float* arow = g_feats + (size_t)(m0 + am) * FEAT_PAD;

    for (int it = 0; it < 37; ++it) {
        const int k0 = it * 16;
        // ---- load A (128x16) -> frag-major tf32 (rows padded to 592, pad=0)
        {
            const float4 v0 = *(const float4*)(arow + k0 + kcA * 8);
            const float4 v1 = *(const float4*)(arow + k0 + kcA * 8 + 4);
            A_s[baseA + 0 * 4 + 0] = f2tf32(v0.x);
            A_s[baseA + 1 * 4 + 0] = f2tf32(v0.y);
            A_s[baseA + 2 * 4 + 0] = f2tf32(v0.z);
            A_s[baseA + 3 * 4 + 0] = f2tf32(v0.w);
            A_s[baseA + 0 * 4 + 2] = f2tf32(v1.x);
            A_s[baseA + 1 * 4 + 2] = f2tf32(v1.y);
            A_s[baseA + 2 * 4 + 2] = f2tf32(v1.z);
            A_s[baseA + 3 * 4 + 2] = f2tf32(v1.w);
        }
        // ---- load B (16x192, zero-pad k>=584) -> frag-major tf32
        #pragma unroll
        for (int j = 0; j < 12; j++) {
            const int flat = j * 256 + t;
            const int kk = flat / 192, n = flat - kk * 192;
            const int k = k0 + kk;
            float v = 0.f;
            if (k < 584)
                v = (n < 128) ? __ldg(ptw1 + (size_t)k * 128 + n)
                              : __ldg(cfw1 + (size_t)k * 64 + (n - 128));
            const int kc = kk >> 3, c = kk & 7;
            B_s[((kc * 24 + (n >> 3)) * 32 + (n & 7) * 4 + (c & 3)) * 2 + (c >> 2)] = f2tf32(v);
        }
        __syncthreads();
        // ---- mma
        #pragma unroll
        for (int kc = 0; kc < 2; kc++) {
            unsigned af[2][4];
            #pragma unroll
            for (int i = 0; i < 2; i++) {
                const uint4 v = *(const uint4*)(A_s + ((kc * 8 + wm * 2 + i) * 32 + lane) * 4);
                af[i][0] = v.x; af[i][1] = v.y; af[i][2] = v.z; af[i][3] = v.w;
            }
            #pragma unroll
            for (int j = 0; j < 12; j++) {
                const uint2 b = *(const uint2*)(B_s + ((kc * 24 + wn * 12 + j) * 32 + lane) * 2);
                #pragma unroll
                for (int i = 0; i < 2; i++) {
                    asm volatile(
                        "mma.sync.aligned.m16n8k8.row.col.f32.tf32.tf32.f32 "
                        "{%0,%1,%2,%3}, {%4,%5,%6,%7}, {%8,%9}, {%0,%1,%2,%3};"
                        : "+f"(acc[i][j][0]), "+f"(acc[i][j][1]),
                          "+f"(acc[i][j][2]), "+f"(acc[i][j][3])
                        : "r"(af[i][0]), "r"(af[i][1]), "r"(af[i][2]), "r"(af[i][3]),
                          "r"(b.x), "r"(b.y));
                }
            }
        }
        __syncthreads();
    }

    // ---- epilogue: bias + relu -> C1s (aliases A_s/B_s; all reads done)
    #pragma unroll
    for (int i = 0; i < 2; i++)
        #pragma unroll
        for (int j = 0; j < 12; j++)
            #pragma unroll
            for (int r = 0; r < 4; r++) {
                const int m = wm * 32 + i * 16 + ((r >> 1) << 3) + g;
                const int n = wn * 96 + j * 8 + tg * 2 + (r & 1);
                C1s[m * 196 + n] = fmaxf(acc[i][j][r] + BiasS[n], 0.f);
            }
    __syncthreads();

    // ---- phase B: heads. warp w -> samples w*16 .. w*16+15
    for (int i = 0; i < 16; i++) {
        const int ml = warp * 16 + i;
        const float* c1 = C1s + ml * 196;
        float a0 = B2s[lane], a1 = B2s[lane + 32];
        #pragma unroll 8
        for (int k = 0; k < 128; k++) {
            const float h = c1[k];
            a0 = fmaf(h, W2s[k * 64 + lane], a0);
            a1 = fmaf(h, W2s[k * 64 + lane + 32], a1);
        }
        a0 = fmaxf(a0, 0.f); a1 = fmaxf(a1, 0.f);

        float l0 = a0 * W3s[lane * 2]     + a1 * W3s[(lane + 32) * 2];
        float l1 = a0 * W3s[lane * 2 + 1] + a1 * W3s[(lane + 32) * 2 + 1];
        float cc = c1[128 + lane] * CW2s[lane] + c1[160 + lane] * CW2s[lane + 32];

        #pragma unroll
        for (int off = 16; off; off >>= 1) {
            l0 += __shfl_xor_sync(0xffffffffu, l0, off);
            l1 += __shfl_xor_sync(0xffffffffu, l1, off);
            cc += __shfl_xor_sync(0xffffffffu, cc, off);
        }
        if (lane == 0) {
            l0 += __ldg(ptb3 + 0); l1 += __ldg(ptb3 + 1);
            const float mx = fmaxf(l0, l1);
            const float e0 = expf(l0 - mx), e1 = expf(l1 - mx);
            const float inv = 1.f / (e0 + e1);
            const float conf = 1.f / (1.f + expf(-(cc + __ldg(cfb2))));
            out[(size_t)(m0 + ml) * 3 + 0] = e0 * inv;
            out[(size_t)(m0 + ml) * 3 + 1] = e1 * inv;
            out[(size_t)(m0 + ml) * 3 + 2] = conf;
        }
    }
}

// ---------------------------------------------------------------------------
extern "C" void kernel_launch(void* const* d_in, const int* in_sizes, int n_in,
                              void* d_out, int out_size)
{
    const float* board = (const float*)d_in[0];
    // d_in[1] = target_positions (int64) — mathematically unused
    const float* c1w = (const float*)d_in[2];  const float* c1b = (const float*)d_in[3];
    const float* c2w = (const float*)d_in[4];  const float* c2b = (const float*)d_in[5];
    const float* c3w = (const float*)d_in[6];  const float* c3b = (const float*)d_in[7];
    const float* qp  = (const float*)d_in[8];
    const float* ptw1 = (const float*)d_in[9];  const float* ptb1 = (const float*)d_in[10];
    const float* ptw2 = (const float*)d_in[11]; const float* ptb2 = (const float*)d_in[12];
    const float* ptw3 = (const float*)d_in[13]; const float* ptb3 = (const float*)d_in[14];
    const float* cfw1 = (const float*)d_in[15]; const float* cfb1 = (const float*)d_in[16];
    const float* cfw2 = (const float*)d_in[17]; const float* cfb2 = (const float*)d_in[18];

    int B = in_sizes[0] / 108;
    if (B > BATCH_MAX) B = BATCH_MAX;

    static bool attr_done = false;
    if (!attr_done) {
        cudaFuncSetAttribute(k_conv, cudaFuncAttributeMaxDynamicSharedMemorySize, 4 * 2016 * 8);
        cudaFuncSetAttribute(k_fc1, cudaFuncAttributeMaxDynamicSharedMemorySize, FC1_SMEM);
        attr_done = true;
    }

    const int pairs = (B + 1) / 2;
    k_wt<<<72, 256>>>(c1w, c2w, c3w);
    k_conv<<<(pairs + 3) / 4, 128, 4 * 2016 * 8>>>(board, c1b, c2b, c3b, qp, B);
    k_fc1<<<B / 128, 256, FC1_SMEM>>>(ptw1, ptb1, cfw1, cfb1,
                                      ptw2, ptb2, ptw3, ptb3, cfw2, cfb2,
                                      (float*)d_out);
}

// round 6
// speedup vs baseline: 1.1953x; 1.1953x over previous
#include <cuda_runtime.h>
#include <math.h>

#define BATCH_MAX 65536
#define FEAT 584
#define FEAT_PAD 592

typedef unsigned long long u64t;

__device__ float g_feats[(size_t)BATCH_MAX * FEAT_PAD + 16]; // +16 pad for float4 tails

// Transposed weight copies (lane-coalesced layouts)
__device__ float g_w1t[27 * 16];        // [tap][co]
__device__ float g_w2t[144 * 32];       // [ci*9+tap][co]
__device__ float g_w3p[288 * 64];       // [(r*32+p)*2+half] : float2 per (r, co-pair)
__device__ unsigned g_bfrag[74 * 24 * 64]; // fc1 B, tf32 fragment-major

// ---- packed f32x2 helpers -------------------------------------------------
__device__ __forceinline__ float2 ffma2(float2 a, float2 b, float2 c) {
    u64t ua = *(u64t*)&a, ub = *(u64t*)&b, uc = *(u64t*)&c, ud;
    asm("fma.rn.f32x2 %0, %1, %2, %3;" : "=l"(ud) : "l"(ua), "l"(ub), "l"(uc));
    return *(float2*)&ud;
}
__device__ __forceinline__ float2 bcast2(float w) { return make_float2(w, w); }
__device__ __forceinline__ float2 fmax2(float2 a, float2 b) {
    return make_float2(fmaxf(a.x, b.x), fmaxf(a.y, b.y));
}
__device__ __forceinline__ unsigned f2tf32(float v) {
    unsigned o; asm("cvt.rna.tf32.f32 %0, %1;" : "=r"(o) : "f"(v)); return o;
}

// ---------------------------------------------------------------------------
// Kernel 0a: transpose conv weights.
// ---------------------------------------------------------------------------
__global__ void k_wt(const float* __restrict__ w1,
                     const float* __restrict__ w2,
                     const float* __restrict__ w3)
{
    const int i = blockIdx.x * 256 + threadIdx.x;
    if (i < 432)   { int co = i / 27,  r = i - co * 27;  g_w1t[r * 16 + co] = w1[i]; }
    if (i < 4608)  { int co = i / 144, r = i - co * 144; g_w2t[r * 32 + co] = w2[i]; }
    if (i < 18432) {
        int co = i / 288, r = i - co * 288;
        g_w3p[(r * 32 + (co >> 1)) * 2 + (co & 1)] = w3[i];
    }
}

// ---------------------------------------------------------------------------
// Kernel 0b: bake fc1 B = [pt_w1 | cf_w1] into tf32 fragment-major layout.
// word index = ((K8*24 + j)*32 + lane)*2 + r  ;  k = K8*8 + r*4 + (lane&3),
// n = j*8 + (lane>>2)  (zero-pad k >= 584)
// ---------------------------------------------------------------------------
__global__ void k_wb(const float* __restrict__ ptw1, const float* __restrict__ cfw1)
{
    const int idx = blockIdx.x * 256 + threadIdx.x;
    if (idx >= 74 * 24 * 64) return;
    const int r = idx & 1;
    const int l = (idx >> 1) & 31;
    const int j = (idx >> 6) % 24;
    const int K8 = idx / (24 * 64);
    const int k = K8 * 8 + r * 4 + (l & 3);
    const int n = j * 8 + (l >> 2);
    float v = 0.f;
    if (k < 584)
        v = (n < 128) ? ptw1[(size_t)k * 128 + n] : cfw1[(size_t)k * 64 + (n - 128)];
    g_bfrag[idx] = f2tf32(v);
}

// ---------------------------------------------------------------------------
// conv2 x-half (unchanged)
// ---------------------------------------------------------------------------
template<int C0, int WIN, int WOUT>
__device__ __forceinline__ void conv2_part(
    const float2* __restrict__ h1p, float2 bias, int lane, float2* __restrict__ pp)
{
    float2 acc[6][WOUT];
    #pragma unroll
    for (int y = 0; y < 6; y++)
        #pragma unroll
        for (int x = 0; x < WOUT; x++) acc[y][x] = bias;

    for (int ci = 0; ci < 16; ci++) {
        float2 w[9];
        #pragma unroll
        for (int i = 0; i < 9; i++) w[i] = bcast2(__ldg(g_w2t + (ci * 9 + i) * 32 + lane));
        const float2* hr = h1p + ci * 64;
        float2 r[3][WIN];
        #pragma unroll
        for (int j = 0; j < WIN; j++) { r[0][j] = hr[C0 + j]; r[1][j] = hr[8 + C0 + j]; }
        #pragma unroll
        for (int y = 0; y < 6; y++) {
            #pragma unroll
            for (int j = 0; j < WIN; j++) r[(y + 2) % 3][j] = hr[(y + 2) * 8 + C0 + j];
            #pragma unroll
            for (int x = 0; x < WOUT; x++) {
                float2 a = acc[y][x];
                a = ffma2(r[(y + 0) % 3][x + 0], w[0], a);
                a = ffma2(r[(y + 0) % 3][x + 1], w[1], a);
                a = ffma2(r[(y + 0) % 3][x + 2], w[2], a);
                a = ffma2(r[(y + 1) % 3][x + 0], w[3], a);
                a = ffma2(r[(y + 1) % 3][x + 1], w[4], a);
                a = ffma2(r[(y + 1) % 3][x + 2], w[5], a);
                a = ffma2(r[(y + 2) % 3][x + 0], w[6], a);
                a = ffma2(r[(y + 2) % 3][x + 1], w[7], a);
                a = ffma2(r[(y + 2) % 3][x + 2], w[8], a);
                acc[y][x] = a;
            }
        }
    }
    #pragma unroll
    for (int py = 0; py < 3; py++)
        #pragma unroll
        for (int pxl = 0; pxl < WOUT / 2; pxl++) {
            float2 m = fmax2(fmax2(acc[2 * py][2 * pxl], acc[2 * py][2 * pxl + 1]),
                             fmax2(acc[2 * py + 1][2 * pxl], acc[2 * py + 1][2 * pxl + 1]));
            m = fmax2(m, make_float2(0.f, 0.f));
            const int px = C0 / 2 + pxl;
            pp[lane * 25 + (py + 1) * 5 + (px + 1)] = m;
        }
}

// ---------------------------------------------------------------------------
// Kernel 1: conv pipeline + quantum sim
// ---------------------------------------------------------------------------
__global__ __launch_bounds__(128) void k_conv(
    const float* __restrict__ board,
    const float* __restrict__ b1,
    const float* __restrict__ b2,
    const float* __restrict__ b3,
    const float* __restrict__ qp, int nsamp)
{
    extern __shared__ float2 smc[];
    const int warp = threadIdx.x >> 5;
    const int lane = threadIdx.x & 31;
    const int pidx = blockIdx.x * 4 + warp;
    const int s0 = 2 * pidx;
    if (s0 >= nsamp) return;
    const bool has2 = (s0 + 1 < nsamp);

    float2* inp = smc + (size_t)warp * 2016;
    float2* h1p = inp + 192;
    float2* pp  = inp + 1216;

    const float* bs0 = board + (size_t)s0 * 108;
    const float* bs1 = has2 ? bs0 + 108 : bs0;

    #pragma unroll
    for (int i = lane; i < 2016; i += 32) inp[i] = make_float2(0.f, 0.f);
    __syncwarp();

    for (int i = lane; i < 108; i += 32) {
        int ci = i / 36, r = i - ci * 36;
        int y = r / 6, x = r - y * 6;
        inp[ci * 64 + (y + 1) * 8 + (x + 1)] = make_float2(bs0[i], bs1[i]);
    }

    // quantum sim + zero the 8-float pad
    if (lane < 16) {
        const int smp = lane >> 3, qb = lane & 7;
        const int sg = s0 + smp;
        if (sg < nsamp) {
            const float* bq = board + (size_t)sg * 108;
            float xv = bq[qb], xn = bq[(qb + 1) & 7];
            float q = 0.f;
            #pragma unroll
            for (int l = 0; l < 3; l++) {
                float r0 = __ldg(qp + (l * 8 + qb) * 3 + 0);
                float r1 = __ldg(qp + (l * 8 + qb) * 3 + 1);
                float r2 = __ldg(qp + (l * 8 + qb) * 3 + 2);
                q = sinf(r0 * xv) * cosf(r1 * xn) + tanhf(r2 * q);
            }
            g_feats[(size_t)sg * FEAT_PAD + 576 + qb] = q;
            g_feats[(size_t)sg * FEAT_PAD + 584 + qb] = 0.f;
        }
    }
    __syncwarp();

    {   // conv1
        const int co = lane & 15, half = lane >> 4;
        float2 w[27];
        #pragma unroll
        for (int i = 0; i < 27; i++) w[i] = bcast2(__ldg(g_w1t + i * 16 + co));
        const float2 bias = bcast2(__ldg(b1 + co));
        #pragma unroll
        for (int p = 0; p < 18; p++) {
            const int yy = half * 3 + p / 6;
            const int xx = p % 6;
            const int y8 = yy * 8;
            float2 a = bias;
            #pragma unroll
            for (int ci = 0; ci < 3; ci++)
                #pragma unroll
                for (int ky = 0; ky < 3; ky++)
                    #pragma unroll
                    for (int kx = 0; kx < 3; kx++)
                        a = ffma2(inp[ci * 64 + y8 + ky * 8 + xx + kx],
                                  w[ci * 9 + ky * 3 + kx], a);
            h1p[co * 64 + y8 + 8 + xx + 1] = fmax2(a, make_float2(0.f, 0.f));
        }
    }
    __syncwarp();

    {   // conv2 (+relu+pool)
        const float2 bias2 = bcast2(__ldg(b2 + lane));
        conv2_part<0, 6, 4>(h1p, bias2, lane, pp);
        conv2_part<4, 4, 2>(h1p, bias2, lane, pp);
    }
    __syncwarp();

    {   // conv3: lane handles co = 2*lane, 2*lane+1 (paired weights, LDG.64)
        float2 acc0[9], acc1[9];
        const float2 bb = __ldg((const float2*)b3 + lane);
        const float2 bz0 = bcast2(bb.x), bz1 = bcast2(bb.y);
        #pragma unroll
        for (int i = 0; i < 9; i++) { acc0[i] = bz0; acc1[i] = bz1; }

        const float2* w3p = (const float2*)g_w3p;
        for (int ci = 0; ci < 32; ci++) {
            float2 wa[9], wb[9];
            #pragma unroll
            for (int i = 0; i < 9; i++) {
                const float2 wv = __ldg(w3p + (ci * 9 + i) * 32 + lane);
                wa[i] = bcast2(wv.x); wb[i] = bcast2(wv.y);
            }
            const float2* ps = pp + ci * 25;
            float2 r[3][5];
            #pragma unroll
            for (int j = 0; j < 5; j++) { r[0][j] = ps[j]; r[1][j] = ps[5 + j]; }
            #pragma unroll
            for (int y = 0; y < 3; y++) {
                #pragma unroll
                for (int j = 0; j < 5; j++) r[(y + 2) % 3][j] = ps[(y + 2) * 5 + j];
                #pragma unroll
                for (int x = 0; x < 3; x++) {
                    float2 a0 = acc0[y * 3 + x], a1 = acc1[y * 3 + x];
                    #pragma unroll
                    for (int ky = 0; ky < 3; ky++)
                        #pragma unroll
                        for (int kx = 0; kx < 3; kx++) {
                            const float2 v = r[(y + ky) % 3][x + kx];
                            a0 = ffma2(v, wa[ky * 3 + kx], a0);
                            a1 = ffma2(v, wb[ky * 3 + kx], a1);
                        }
                    acc0[y * 3 + x] = a0; acc1[y * 3 + x] = a1;
                }
            }
        }
        float* f0 = g_feats + (size_t)s0 * FEAT_PAD;
        float* f1 = f0 + FEAT_PAD;
        const int co0 = 2 * lane, co1 = 2 * lane + 1;
        #pragma unroll
        for (int i = 0; i < 9; i++) {
            float2 v0 = fmax2(acc0[i], make_float2(0.f, 0.f));
            float2 v1 = fmax2(acc1[i], make_float2(0.f, 0.f));
            f0[co0 * 9 + i] = v0.x;
            f0[co1 * 9 + i] = v1.x;
            if (has2) { f1[co0 * 9 + i] = v0.y; f1[co1 * 9 + i] = v1.y; }
        }
    }
}

// ---------------------------------------------------------------------------
// Kernel 2 (fused, tf32 mma, pipelined): C1 = relu(feats @ B + bias), heads.
// BM=128, N=192, K=592, BK=16. 8 warps, warp-tile 32x96.
// B comes pre-baked fragment-major from g_bfrag (3x LDG.128/thread/iter).
// ---------------------------------------------------------------------------
#define FC1_SMEM (33728 * 4)

__global__ __launch_bounds__(256) void k_fc1(
    const float* __restrict__ ptb1, const float* __restrict__ cfb1,
    const float* __restrict__ ptw2, const float* __restrict__ ptb2,
    const float* __restrict__ ptw3, const float* __restrict__ ptb3,
    const float* __restrict__ cfw2, const float* __restrict__ cfb2,
    float* __restrict__ out)
{
    extern __shared__ float sfc[];
    unsigned* A_s = (unsigned*)sfc;            // 2048
    unsigned* B_s = (unsigned*)(sfc + 2048);   // 3072
    float* C1s    = sfc;                       // 25088 (post-GEMM alias)
    float* W2s    = sfc + 25088;               // 8192 (paired: [k*32+l] -> {co=l, co=l+32})
    float* BiasS  = sfc + 33280;               // 192
    float* W3s    = sfc + 33472;               // 128
    float* CW2s   = sfc + 33600;               // 64
    float* B2s    = sfc + 33664;               // 64 (paired)

    const int t = threadIdx.x;
    const int m0 = blockIdx.x * 128;
    const int warp = t >> 5, lane = t & 31;
    const int wm = warp >> 1, wn = warp & 1;
    const int g = lane >> 2, tg = lane & 3;

    // preload head weights (paired layouts) + biases
    for (int i = t; i < 4096; i += 256) {
        const int k = i >> 5, l = i & 31;
        W2s[i * 2]     = __ldg(ptw2 + k * 64 + l);
        W2s[i * 2 + 1] = __ldg(ptw2 + k * 64 + l + 32);
    }
    if (t < 192) BiasS[t] = (t < 128) ? __ldg(ptb1 + t) : __ldg(cfb1 + t - 128);
    if (t < 128) W3s[t] = __ldg(ptw3 + t);
    if (t < 64)  CW2s[t] = __ldg(cfw2 + t);
    if (t < 32)  { B2s[t * 2] = __ldg(ptb2 + t); B2s[t * 2 + 1] = __ldg(ptb2 + t + 32); }

    float acc[2][12][4];
    #pragma unroll
    for (int i = 0; i < 2; i++)
        #pragma unroll
        for (int j = 0; j < 12; j++)
            #pragma unroll
            for (int r = 0; r < 4; r++) acc[i][j][r] = 0.f;

    // A-loader mapping
    const int am = t >> 1;
    const int kcA = t & 1;
    const int rA = am & 15, mtA = am >> 4;
    const int baseA = ((kcA * 8 + mtA) * 32 + (rA & 7) * 4) * 4 + (rA >> 3);
    const float* arow = g_feats + (size_t)(m0 + am) * FEAT_PAD + kcA * 8;

    // prefetch it=0
    float4 av0 = *(const float4*)(arow);
    float4 av1 = *(const float4*)(arow + 4);
    uint4 bv0 = *(const uint4*)(g_bfrag + t * 12);
    uint4 bv1 = *(const uint4*)(g_bfrag + t * 12 + 4);
    uint4 bv2 = *(const uint4*)(g_bfrag + t * 12 + 8);

    for (int it = 0; it < 37; ++it) {
        // ---- store staged tiles
        A_s[baseA + 0 * 4 + 0] = f2tf32(av0.x);
        A_s[baseA + 1 * 4 + 0] = f2tf32(av0.y);
        A_s[baseA + 2 * 4 + 0] = f2tf32(av0.z);
        A_s[baseA + 3 * 4 + 0] = f2tf32(av0.w);
        A_s[baseA + 0 * 4 + 2] = f2tf32(av1.x);
        A_s[baseA + 1 * 4 + 2] = f2tf32(av1.y);
        A_s[baseA + 2 * 4 + 2] = f2tf32(av1.z);
        A_s[baseA + 3 * 4 + 2] = f2tf32(av1.w);
        *(uint4*)(B_s + t * 12)     = bv0;
        *(uint4*)(B_s + t * 12 + 4) = bv1;
        *(uint4*)(B_s + t * 12 + 8) = bv2;
        __syncthreads();
        // ---- prefetch next tiles (hidden under mma)
        if (it < 36) {
            av0 = *(const float4*)(arow + (it + 1) * 16);
            av1 = *(const float4*)(arow + (it + 1) * 16 + 4);
            const unsigned* bsrc = g_bfrag + (it + 1) * 3072 + t * 12;
            bv0 = *(const uint4*)(bsrc);
            bv1 = *(const uint4*)(bsrc + 4);
            bv2 = *(const uint4*)(bsrc + 8);
        }
        // ---- mma
        #pragma unroll
        for (int kc = 0; kc < 2; kc++) {
            unsigned af[2][4];
            #pragma unroll
            for (int i = 0; i < 2; i++) {
                const uint4 v = *(const uint4*)(A_s + ((kc * 8 + wm * 2 + i) * 32 + lane) * 4);
                af[i][0] = v.x; af[i][1] = v.y; af[i][2] = v.z; af[i][3] = v.w;
            }
            #pragma unroll
            for (int j = 0; j < 12; j++) {
                const uint2 b = *(const uint2*)(B_s + ((kc * 24 + wn * 12 + j) * 32 + lane) * 2);
                #pragma unroll
                for (int i = 0; i < 2; i++) {
                    asm volatile(
                        "mma.sync.aligned.m16n8k8.row.col.f32.tf32.tf32.f32 "
                        "{%0,%1,%2,%3}, {%4,%5,%6,%7}, {%8,%9}, {%0,%1,%2,%3};"
                        : "+f"(acc[i][j][0]), "+f"(acc[i][j][1]),
                          "+f"(acc[i][j][2]), "+f"(acc[i][j][3])
                        : "r"(af[i][0]), "r"(af[i][1]), "r"(af[i][2]), "r"(af[i][3]),
                          "r"(b.x), "r"(b.y));
                }
            }
        }
        __syncthreads();
    }

    // ---- epilogue: bias + relu -> C1s
    #pragma unroll
    for (int i = 0; i < 2; i++)
        #pragma unroll
        for (int j = 0; j < 12; j++)
            #pragma unroll
            for (int r = 0; r < 4; r++) {
                const int m = wm * 32 + i * 16 + ((r >> 1) << 3) + g;
                const int n = wn * 96 + j * 8 + tg * 2 + (r & 1);
                C1s[m * 196 + n] = fmaxf(acc[i][j][r] + BiasS[n], 0.f);
            }
    __syncthreads();

    // ---- heads: warp w -> samples w*16 .. w*16+15 (paired W2, ffma2)
    const float2* W2p = (const float2*)W2s;
    for (int i = 0; i < 16; i++) {
        const int ml = warp * 16 + i;
        const float* c1 = C1s + ml * 196;
        float2 a01 = ((const float2*)B2s)[lane];
        #pragma unroll 4
        for (int k4 = 0; k4 < 32; k4++) {
            const float4 h = *(const float4*)(c1 + k4 * 4);
            a01 = ffma2(bcast2(h.x), W2p[(k4 * 4 + 0) * 32 + lane], a01);
            a01 = ffma2(bcast2(h.y), W2p[(k4 * 4 + 1) * 32 + lane], a01);
            a01 = ffma2(bcast2(h.z), W2p[(k4 * 4 + 2) * 32 + lane], a01);
            a01 = ffma2(bcast2(h.w), W2p[(k4 * 4 + 3) * 32 + lane], a01);
        }
        const float a0 = fmaxf(a01.x, 0.f), a1 = fmaxf(a01.y, 0.f);

        float l0 = a0 * W3s[lane * 2]     + a1 * W3s[(lane + 32) * 2];
        float l1 = a0 * W3s[lane * 2 + 1] + a1 * W3s[(lane + 32) * 2 + 1];
        float cc = c1[128 + lane] * CW2s[lane] + c1[160 + lane] * CW2s[lane + 32];

        #pragma unroll
        for (int off = 16; off; off >>= 1) {
            l0 += __shfl_xor_sync(0xffffffffu, l0, off);
            l1 += __shfl_xor_sync(0xffffffffu, l1, off);
            cc += __shfl_xor_sync(0xffffffffu, cc, off);
        }
        if (lane == 0) {
            l0 += __ldg(ptb3 + 0); l1 += __ldg(ptb3 + 1);
            const float mx = fmaxf(l0, l1);
            const float e0 = expf(l0 - mx), e1 = expf(l1 - mx);
            const float inv = 1.f / (e0 + e1);
            const float conf = 1.f / (1.f + expf(-(cc + __ldg(cfb2))));
            out[(size_t)(m0 + ml) * 3 + 0] = e0 * inv;
            out[(size_t)(m0 + ml) * 3 + 1] = e1 * inv;
            out[(size_t)(m0 + ml) * 3 + 2] = conf;
        }
    }
}

// ---------------------------------------------------------------------------
extern "C" void kernel_launch(void* const* d_in, const int* in_sizes, int n_in,
                              void* d_out, int out_size)
{
    const float* board = (const float*)d_in[0];
    // d_in[1] = target_positions (int64) — mathematically unused
    const float* c1w = (const float*)d_in[2];  const float* c1b = (const float*)d_in[3];
    const float* c2w = (const float*)d_in[4];  const float* c2b = (const float*)d_in[5];
    const float* c3w = (const float*)d_in[6];  const float* c3b = (const float*)d_in[7];
    const float* qp  = (const float*)d_in[8];
    const float* ptw1 = (const float*)d_in[9];  const float* ptb1 = (const float*)d_in[10];
    const float* ptw2 = (const float*)d_in[11]; const float* ptb2 = (const float*)d_in[12];
    const float* ptw3 = (const float*)d_in[13]; const float* ptb3 = (const float*)d_in[14];
    const float* cfw1 = (const float*)d_in[15]; const float* cfb1 = (const float*)d_in[16];
    const float* cfw2 = (const float*)d_in[17]; const float* cfb2 = (const float*)d_in[18];

    int B = in_sizes[0] / 108;
    if (B > BATCH_MAX) B = BATCH_MAX;

    static bool attr_done = false;
    if (!attr_done) {
        cudaFuncSetAttribute(k_conv, cudaFuncAttributeMaxDynamicSharedMemorySize, 4 * 2016 * 8);
        cudaFuncSetAttribute(k_fc1, cudaFuncAttributeMaxDynamicSharedMemorySize, FC1_SMEM);
        attr_done = true;
    }

    const int pairs = (B + 1) / 2;
    k_wt<<<72, 256>>>(c1w, c2w, c3w);
    k_wb<<<(74 * 24 * 64 + 255) / 256, 256>>>(ptw1, cfw1);
    k_conv<<<(pairs + 3) / 4, 128, 4 * 2016 * 8>>>(board, c1b, c2b, c3b, qp, B);
    k_fc1<<<B / 128, 256, FC1_SMEM>>>(ptb1, cfb1,
                                      ptw2, ptb2, ptw3, ptb3, cfw2, cfb2,
                                      (float*)d_out);
}

// round 7
// speedup vs baseline: 1.2871x; 1.0767x over previous
#include <cuda_runtime.h>
#include <math.h>

#define BATCH_MAX 65536
#define FEAT 584
#define FEAT_PAD 592

typedef unsigned long long u64t;

__device__ float g_feats[(size_t)BATCH_MAX * FEAT_PAD + 16]; // +16 pad for float4 tails

// Transposed weight copies (lane-coalesced layouts)
__device__ float g_w1t[27 * 16];        // [tap][co]
__device__ float g_w2t[144 * 32];       // [ci*9+tap][co]
__device__ float g_w3p[288 * 64];       // [(r*32+p)*2+half] : float2 per (r, co-pair)
__device__ unsigned g_bfrag[74 * 24 * 64];  // fc1 B, tf32 fragment-major
__device__ unsigned g_w2frag[16 * 8 * 64];  // heads W2, tf32 fragment-major

// ---- packed f32x2 helpers -------------------------------------------------
__device__ __forceinline__ float2 ffma2(float2 a, float2 b, float2 c) {
    u64t ua = *(u64t*)&a, ub = *(u64t*)&b, uc = *(u64t*)&c, ud;
    asm("fma.rn.f32x2 %0, %1, %2, %3;" : "=l"(ud) : "l"(ua), "l"(ub), "l"(uc));
    return *(float2*)&ud;
}
__device__ __forceinline__ float2 bcast2(float w) { return make_float2(w, w); }
__device__ __forceinline__ float2 fmax2(float2 a, float2 b) {
    return make_float2(fmaxf(a.x, b.x), fmaxf(a.y, b.y));
}
__device__ __forceinline__ unsigned f2tf32(float v) {
    unsigned o; asm("cvt.rna.tf32.f32 %0, %1;" : "=r"(o) : "f"(v)); return o;
}

// ---------------------------------------------------------------------------
// Kernel 0a: transpose conv weights.
// ---------------------------------------------------------------------------
__global__ void k_wt(const float* __restrict__ w1,
                     const float* __restrict__ w2,
                     const float* __restrict__ w3)
{
    const int i = blockIdx.x * 256 + threadIdx.x;
    if (i < 432)   { int co = i / 27,  r = i - co * 27;  g_w1t[r * 16 + co] = w1[i]; }
    if (i < 4608)  { int co = i / 144, r = i - co * 144; g_w2t[r * 32 + co] = w2[i]; }
    if (i < 18432) {
        int co = i / 288, r = i - co * 288;
        g_w3p[(r * 32 + (co >> 1)) * 2 + (co & 1)] = w3[i];
    }
}

// ---------------------------------------------------------------------------
// Kernel 0b: bake fc1 B = [pt_w1 | cf_w1] into tf32 fragment-major layout.
// ---------------------------------------------------------------------------
__global__ void k_wb(const float* __restrict__ ptw1, const float* __restrict__ cfw1)
{
    const int idx = blockIdx.x * 256 + threadIdx.x;
    if (idx >= 74 * 24 * 64) return;
    const int r = idx & 1;
    const int l = (idx >> 1) & 31;
    const int j = (idx >> 6) % 24;
    const int K8 = idx / (24 * 64);
    const int k = K8 * 8 + r * 4 + (l & 3);
    const int n = j * 8 + (l >> 2);
    float v = 0.f;
    if (k < 584)
        v = (n < 128) ? ptw1[(size_t)k * 128 + n] : cfw1[(size_t)k * 64 + (n - 128)];
    g_bfrag[idx] = f2tf32(v);
}

// ---------------------------------------------------------------------------
// Kernel 0c: bake heads W2 (128x64) into tf32 fragment-major layout.
// word idx = ((k8*8 + j)*32 + lane)*2 + r ; k = k8*8+r*4+(lane&3), n = j*8+(lane>>2)
// ---------------------------------------------------------------------------
__global__ void k_wb2(const float* __restrict__ ptw2)
{
    const int idx = blockIdx.x * 256 + threadIdx.x;
    if (idx >= 16 * 8 * 64) return;
    const int r = idx & 1;
    const int l = (idx >> 1) & 31;
    const int j = (idx >> 6) & 7;
    const int k8 = idx >> 9;
    const int k = k8 * 8 + r * 4 + (l & 3);
    const int n = j * 8 + (l >> 2);
    g_w2frag[idx] = f2tf32(ptw2[(size_t)k * 64 + n]);
}

// ---------------------------------------------------------------------------
// conv2 x-half (unchanged)
// ---------------------------------------------------------------------------
template<int C0, int WIN, int WOUT>
__device__ __forceinline__ void conv2_part(
    const float2* __restrict__ h1p, float2 bias, int lane, float2* __restrict__ pp)
{
    float2 acc[6][WOUT];
    #pragma unroll
    for (int y = 0; y < 6; y++)
        #pragma unroll
        for (int x = 0; x < WOUT; x++) acc[y][x] = bias;

    for (int ci = 0; ci < 16; ci++) {
        float2 w[9];
        #pragma unroll
        for (int i = 0; i < 9; i++) w[i] = bcast2(__ldg(g_w2t + (ci * 9 + i) * 32 + lane));
        const float2* hr = h1p + ci * 64;
        float2 r[3][WIN];
        #pragma unroll
        for (int j = 0; j < WIN; j++) { r[0][j] = hr[C0 + j]; r[1][j] = hr[8 + C0 + j]; }
        #pragma unroll
        for (int y = 0; y < 6; y++) {
            #pragma unroll
            for (int j = 0; j < WIN; j++) r[(y + 2) % 3][j] = hr[(y + 2) * 8 + C0 + j];
            #pragma unroll
            for (int x = 0; x < WOUT; x++) {
                float2 a = acc[y][x];
                a = ffma2(r[(y + 0) % 3][x + 0], w[0], a);
                a = ffma2(r[(y + 0) % 3][x + 1], w[1], a);
                a = ffma2(r[(y + 0) % 3][x + 2], w[2], a);
                a = ffma2(r[(y + 1) % 3][x + 0], w[3], a);
                a = ffma2(r[(y + 1) % 3][x + 1], w[4], a);
                a = ffma2(r[(y + 1) % 3][x + 2], w[5], a);
                a = ffma2(r[(y + 2) % 3][x + 0], w[6], a);
                a = ffma2(r[(y + 2) % 3][x + 1], w[7], a);
                a = ffma2(r[(y + 2) % 3][x + 2], w[8], a);
                acc[y][x] = a;
            }
        }
    }
    #pragma unroll
    for (int py = 0; py < 3; py++)
        #pragma unroll
        for (int pxl = 0; pxl < WOUT / 2; pxl++) {
            float2 m = fmax2(fmax2(acc[2 * py][2 * pxl], acc[2 * py][2 * pxl + 1]),
                             fmax2(acc[2 * py + 1][2 * pxl], acc[2 * py + 1][2 * pxl + 1]));
            m = fmax2(m, make_float2(0.f, 0.f));
            const int px = C0 / 2 + pxl;
            pp[lane * 25 + (py + 1) * 5 + (px + 1)] = m;
        }
}

// ---------------------------------------------------------------------------
// Kernel 1: conv pipeline + quantum sim (unchanged from round 6)
// ---------------------------------------------------------------------------
__global__ __launch_bounds__(128) void k_conv(
    const float* __restrict__ board,
    const float* __restrict__ b1,
    const float* __restrict__ b2,
    const float* __restrict__ b3,
    const float* __restrict__ qp, int nsamp)
{
    extern __shared__ float2 smc[];
    const int warp = threadIdx.x >> 5;
    const int lane = threadIdx.x & 31;
    const int pidx = blockIdx.x * 4 + warp;
    const int s0 = 2 * pidx;
    if (s0 >= nsamp) return;
    const bool has2 = (s0 + 1 < nsamp);

    float2* inp = smc + (size_t)warp * 2016;
    float2* h1p = inp + 192;
    float2* pp  = inp + 1216;

    const float* bs0 = board + (size_t)s0 * 108;
    const float* bs1 = has2 ? bs0 + 108 : bs0;

    #pragma unroll
    for (int i = lane; i < 2016; i += 32) inp[i] = make_float2(0.f, 0.f);
    __syncwarp();

    for (int i = lane; i < 108; i += 32) {
        int ci = i / 36, r = i - ci * 36;
        int y = r / 6, x = r - y * 6;
        inp[ci * 64 + (y + 1) * 8 + (x + 1)] = make_float2(bs0[i], bs1[i]);
    }

    if (lane < 16) {
        const int smp = lane >> 3, qb = lane & 7;
        const int sg = s0 + smp;
        if (sg < nsamp) {
            const float* bq = board + (size_t)sg * 108;
            float xv = bq[qb], xn = bq[(qb + 1) & 7];
            float q = 0.f;
            #pragma unroll
            for (int l = 0; l < 3; l++) {
                float r0 = __ldg(qp + (l * 8 + qb) * 3 + 0);
                float r1 = __ldg(qp + (l * 8 + qb) * 3 + 1);
                float r2 = __ldg(qp + (l * 8 + qb) * 3 + 2);
                q = sinf(r0 * xv) * cosf(r1 * xn) + tanhf(r2 * q);
            }
            g_feats[(size_t)sg * FEAT_PAD + 576 + qb] = q;
            g_feats[(size_t)sg * FEAT_PAD + 584 + qb] = 0.f;
        }
    }
    __syncwarp();

    {   // conv1
        const int co = lane & 15, half = lane >> 4;
        float2 w[27];
        #pragma unroll
        for (int i = 0; i < 27; i++) w[i] = bcast2(__ldg(g_w1t + i * 16 + co));
        const float2 bias = bcast2(__ldg(b1 + co));
        #pragma unroll
        for (int p = 0; p < 18; p++) {
            const int yy = half * 3 + p / 6;
            const int xx = p % 6;
            const int y8 = yy * 8;
            float2 a = bias;
            #pragma unroll
            for (int ci = 0; ci < 3; ci++)
                #pragma unroll
                for (int ky = 0; ky < 3; ky++)
                    #pragma unroll
                    for (int kx = 0; kx < 3; kx++)
                        a = ffma2(inp[ci * 64 + y8 + ky * 8 + xx + kx],
                                  w[ci * 9 + ky * 3 + kx], a);
            h1p[co * 64 + y8 + 8 + xx + 1] = fmax2(a, make_float2(0.f, 0.f));
        }
    }
    __syncwarp();

    {   // conv2 (+relu+pool)
        const float2 bias2 = bcast2(__ldg(b2 + lane));
        conv2_part<0, 6, 4>(h1p, bias2, lane, pp);
        conv2_part<4, 4, 2>(h1p, bias2, lane, pp);
    }
    __syncwarp();

    {   // conv3: lane handles co = 2*lane, 2*lane+1 (paired weights, LDG.64)
        float2 acc0[9], acc1[9];
        const float2 bb = __ldg((const float2*)b3 + lane);
        const float2 bz0 = bcast2(bb.x), bz1 = bcast2(bb.y);
        #pragma unroll
        for (int i = 0; i < 9; i++) { acc0[i] = bz0; acc1[i] = bz1; }

        const float2* w3p = (const float2*)g_w3p;
        for (int ci = 0; ci < 32; ci++) {
            float2 wa[9], wb[9];
            #pragma unroll
            for (int i = 0; i < 9; i++) {
                const float2 wv = __ldg(w3p + (ci * 9 + i) * 32 + lane);
                wa[i] = bcast2(wv.x); wb[i] = bcast2(wv.y);
            }
            const float2* ps = pp + ci * 25;
            float2 r[3][5];
            #pragma unroll
            for (int j = 0; j < 5; j++) { r[0][j] = ps[j]; r[1][j] = ps[5 + j]; }
            #pragma unroll
            for (int y = 0; y < 3; y++) {
                #pragma unroll
                for (int j = 0; j < 5; j++) r[(y + 2) % 3][j] = ps[(y + 2) * 5 + j];
                #pragma unroll
                for (int x = 0; x < 3; x++) {
                    float2 a0 = acc0[y * 3 + x], a1 = acc1[y * 3 + x];
                    #pragma unroll
                    for (int ky = 0; ky < 3; ky++)
                        #pragma unroll
                        for (int kx = 0; kx < 3; kx++) {
                            const float2 v = r[(y + ky) % 3][x + kx];
                            a0 = ffma2(v, wa[ky * 3 + kx], a0);
                            a1 = ffma2(v, wb[ky * 3 + kx], a1);
                        }
                    acc0[y * 3 + x] = a0; acc1[y * 3 + x] = a1;
                }
            }
        }
        float* f0 = g_feats + (size_t)s0 * FEAT_PAD;
        float* f1 = f0 + FEAT_PAD;
        const int co0 = 2 * lane, co1 = 2 * lane + 1;
        #pragma unroll
        for (int i = 0; i < 9; i++) {
            float2 v0 = fmax2(acc0[i], make_float2(0.f, 0.f));
            float2 v1 = fmax2(acc1[i], make_float2(0.f, 0.f));
            f0[co0 * 9 + i] = v0.x;
            f0[co1 * 9 + i] = v1.x;
            if (has2) { f1[co0 * 9 + i] = v0.y; f1[co1 * 9 + i] = v1.y; }
        }
    }
}

// ---------------------------------------------------------------------------
// Kernel 2 (fused, all-tensor-core): C1 = relu(feats @ B + bias), then heads
// via a second mma GEMM (M=16/warp, N=64, K=128) with logits computed
// directly from C fragments. Smem = C1s (100KB) + small tables.
// ---------------------------------------------------------------------------
#define FC1_SMEM (25536 * 4)

__global__ __launch_bounds__(256) void k_fc1(
    const float* __restrict__ ptb1, const float* __restrict__ cfb1,
    const float* __restrict__ ptb2,
    const float* __restrict__ ptw3, const float* __restrict__ ptb3,
    const float* __restrict__ cfw2, const float* __restrict__ cfb2,
    float* __restrict__ out)
{
    extern __shared__ float sfc[];
    unsigned* A_s = (unsigned*)sfc;            // 2048
    unsigned* B_s = (unsigned*)(sfc + 2048);   // 3072
    float* C1s    = sfc;                       // 25088 (post-GEMM alias)
    float* BiasS  = sfc + 25088;               // 192
    float* W3s    = sfc + 25280;               // 128
    float* CW2s   = sfc + 25408;               // 64
    float* B2s    = sfc + 25472;               // 64

    const int t = threadIdx.x;
    const int m0 = blockIdx.x * 128;
    const int warp = t >> 5, lane = t & 31;
    const int wm = warp >> 1, wn = warp & 1;
    const int g = lane >> 2, tg = lane & 3;

    // preload small tables (regions disjoint from A_s/B_s)
    if (t < 192) BiasS[t] = (t < 128) ? __ldg(ptb1 + t) : __ldg(cfb1 + t - 128);
    if (t < 128) W3s[t] = __ldg(ptw3 + t);
    if (t < 64)  { CW2s[t] = __ldg(cfw2 + t); B2s[t] = __ldg(ptb2 + t); }

    float acc[2][12][4];
    #pragma unroll
    for (int i = 0; i < 2; i++)
        #pragma unroll
        for (int j = 0; j < 12; j++)
            #pragma unroll
            for (int r = 0; r < 4; r++) acc[i][j][r] = 0.f;

    // A-loader mapping
    const int am = t >> 1;
    const int kcA = t & 1;
    const int rA = am & 15, mtA = am >> 4;
    const int baseA = ((kcA * 8 + mtA) * 32 + (rA & 7) * 4) * 4 + (rA >> 3);
    const float* arow = g_feats + (size_t)(m0 + am) * FEAT_PAD + kcA * 8;

    // prefetch it=0
    float4 av0 = *(const float4*)(arow);
    float4 av1 = *(const float4*)(arow + 4);
    uint4 bv0 = *(const uint4*)(g_bfrag + t * 12);
    uint4 bv1 = *(const uint4*)(g_bfrag + t * 12 + 4);
    uint4 bv2 = *(const uint4*)(g_bfrag + t * 12 + 8);

    for (int it = 0; it < 37; ++it) {
        A_s[baseA + 0 * 4 + 0] = f2tf32(av0.x);
        A_s[baseA + 1 * 4 + 0] = f2tf32(av0.y);
        A_s[baseA + 2 * 4 + 0] = f2tf32(av0.z);
        A_s[baseA + 3 * 4 + 0] = f2tf32(av0.w);
        A_s[baseA + 0 * 4 + 2] = f2tf32(av1.x);
        A_s[baseA + 1 * 4 + 2] = f2tf32(av1.y);
        A_s[baseA + 2 * 4 + 2] = f2tf32(av1.z);
        A_s[baseA + 3 * 4 + 2] = f2tf32(av1.w);
        *(uint4*)(B_s + t * 12)     = bv0;
        *(uint4*)(B_s + t * 12 + 4) = bv1;
        *(uint4*)(B_s + t * 12 + 8) = bv2;
        __syncthreads();
        if (it < 36) {
            av0 = *(const float4*)(arow + (it + 1) * 16);
            av1 = *(const float4*)(arow + (it + 1) * 16 + 4);
            const unsigned* bsrc = g_bfrag + (it + 1) * 3072 + t * 12;
            bv0 = *(const uint4*)(bsrc);
            bv1 = *(const uint4*)(bsrc + 4);
            bv2 = *(const uint4*)(bsrc + 8);
        }
        #pragma unroll
        for (int kc = 0; kc < 2; kc++) {
            unsigned af[2][4];
            #pragma unroll
            for (int i = 0; i < 2; i++) {
                const uint4 v = *(const uint4*)(A_s + ((kc * 8 + wm * 2 + i) * 32 + lane) * 4);
                af[i][0] = v.x; af[i][1] = v.y; af[i][2] = v.z; af[i][3] = v.w;
            }
            #pragma unroll
            for (int j = 0; j < 12; j++) {
                const uint2 b = *(const uint2*)(B_s + ((kc * 24 + wn * 12 + j) * 32 + lane) * 2);
                #pragma unroll
                for (int i = 0; i < 2; i++) {
                    asm volatile(
                        "mma.sync.aligned.m16n8k8.row.col.f32.tf32.tf32.f32 "
                        "{%0,%1,%2,%3}, {%4,%5,%6,%7}, {%8,%9}, {%0,%1,%2,%3};"
                        : "+f"(acc[i][j][0]), "+f"(acc[i][j][1]),
                          "+f"(acc[i][j][2]), "+f"(acc[i][j][3])
                        : "r"(af[i][0]), "r"(af[i][1]), "r"(af[i][2]), "r"(af[i][3]),
                          "r"(b.x), "r"(b.y));
                }
            }
        }
        __syncthreads();
    }

    // ---- epilogue: bias + relu -> C1s
    #pragma unroll
    for (int i = 0; i < 2; i++)
        #pragma unroll
        for (int j = 0; j < 12; j++)
            #pragma unroll
            for (int r = 0; r < 4; r++) {
                const int m = wm * 32 + i * 16 + ((r >> 1) << 3) + g;
                const int n = wn * 96 + j * 8 + tg * 2 + (r & 1);
                C1s[m * 196 + n] = fmaxf(acc[i][j][r] + BiasS[n], 0.f);
            }
    __syncthreads();

    // ---- heads via mma: warp w -> samples base..base+15; K=128, N=64
    {
        const int base = warp * 16;
        float hacc[8][4];
        #pragma unroll
        for (int j = 0; j < 8; j++)
            #pragma unroll
            for (int r = 0; r < 4; r++) hacc[j][r] = 0.f;

        #pragma unroll 4
        for (int k8 = 0; k8 < 16; k8++) {
            const float* cA = C1s + base * 196 + k8 * 8;
            const unsigned a0 = f2tf32(cA[g * 196 + tg]);
            const unsigned a1 = f2tf32(cA[(g + 8) * 196 + tg]);
            const unsigned a2 = f2tf32(cA[g * 196 + tg + 4]);
            const unsigned a3 = f2tf32(cA[(g + 8) * 196 + tg + 4]);
            #pragma unroll
            for (int j = 0; j < 8; j++) {
                const uint2 b = __ldg((const uint2*)g_w2frag + (k8 * 8 + j) * 32 + lane);
                asm volatile(
                    "mma.sync.aligned.m16n8k8.row.col.f32.tf32.tf32.f32 "
                    "{%0,%1,%2,%3}, {%4,%5,%6,%7}, {%8,%9}, {%0,%1,%2,%3};"
                    : "+f"(hacc[j][0]), "+f"(hacc[j][1]),
                      "+f"(hacc[j][2]), "+f"(hacc[j][3])
                    : "r"(a0), "r"(a1), "r"(a2), "r"(a3),
                      "r"(b.x), "r"(b.y));
            }
        }

        // logits from fragments: rows g (r<2) and g+8 (r>=2)
        float l0g = 0.f, l1g = 0.f, l0h = 0.f, l1h = 0.f;
        #pragma unroll
        for (int j = 0; j < 8; j++)
            #pragma unroll
            for (int r = 0; r < 4; r++) {
                const int n = j * 8 + tg * 2 + (r & 1);
                const float v = fmaxf(hacc[j][r] + B2s[n], 0.f);
                const float w30 = W3s[n * 2], w31 = W3s[n * 2 + 1];
                if (r < 2) { l0g = fmaf(v, w30, l0g); l1g = fmaf(v, w31, l1g); }
                else       { l0h = fmaf(v, w30, l0h); l1h = fmaf(v, w31, l1h); }
            }
        #pragma unroll
        for (int off = 1; off <= 2; off <<= 1) {
            l0g += __shfl_xor_sync(0xffffffffu, l0g, off);
            l1g += __shfl_xor_sync(0xffffffffu, l1g, off);
            l0h += __shfl_xor_sync(0xffffffffu, l0h, off);
            l1h += __shfl_xor_sync(0xffffffffu, l1h, off);
        }
        if (tg == 0) {
            const float b30 = __ldg(ptb3 + 0), b31 = __ldg(ptb3 + 1);
            {   // sample base + g
                const float l0 = l0g + b30, l1 = l1g + b31;
                const float mx = fmaxf(l0, l1);
                const float e0 = expf(l0 - mx), e1 = expf(l1 - mx);
                const float inv = 1.f / (e0 + e1);
                out[(size_t)(m0 + base + g) * 3 + 0] = e0 * inv;
                out[(size_t)(m0 + base + g) * 3 + 1] = e1 * inv;
            }
            {   // sample base + g + 8
                const float l0 = l0h + b30, l1 = l1h + b31;
                const float mx = fmaxf(l0, l1);
                const float e0 = expf(l0 - mx), e1 = expf(l1 - mx);
                const float inv = 1.f / (e0 + e1);
                out[(size_t)(m0 + base + g + 8) * 3 + 0] = e0 * inv;
                out[(size_t)(m0 + base + g + 8) * 3 + 1] = e1 * inv;
            }
        }

        // confidence head (scalar, tiny)
        for (int i = 0; i < 16; i++) {
            const int ml = base + i;
            const float* c1 = C1s + ml * 196;
            float cc = c1[128 + lane] * CW2s[lane] + c1[160 + lane] * CW2s[lane + 32];
            #pragma unroll
            for (int off = 16; off; off >>= 1)
                cc += __shfl_xor_sync(0xffffffffu, cc, off);
            if (lane == 0)
                out[(size_t)(m0 + ml) * 3 + 2] =
                    1.f / (1.f + expf(-(cc + __ldg(cfb2))));
        }
    }
}

// ---------------------------------------------------------------------------
extern "C" void kernel_launch(void* const* d_in, const int* in_sizes, int n_in,
                              void* d_out, int out_size)
{
    const float* board = (const float*)d_in[0];
    // d_in[1] = target_positions (int64) — mathematically unused
    const float* c1w = (const float*)d_in[2];  const float* c1b = (const float*)d_in[3];
    const float* c2w = (const float*)d_in[4];  const float* c2b = (const float*)d_in[5];
    const float* c3w = (const float*)d_in[6];  const float* c3b = (const float*)d_in[7];
    const float* qp  = (const float*)d_in[8];
    const float* ptw1 = (const float*)d_in[9];  const float* ptb1 = (const float*)d_in[10];
    const float* ptw2 = (const float*)d_in[11]; const float* ptb2 = (const float*)d_in[12];
    const float* ptw3 = (const float*)d_in[13]; const float* ptb3 = (const float*)d_in[14];
    const float* cfw1 = (const float*)d_in[15]; const float* cfb1 = (const float*)d_in[16];
    const float* cfw2 = (const float*)d_in[17]; const float* cfb2 = (const float*)d_in[18];

    int B = in_sizes[0] / 108;
    if (B > BATCH_MAX) B = BATCH_MAX;

    static bool attr_done = false;
    if (!attr_done) {
        cudaFuncSetAttribute(k_conv, cudaFuncAttributeMaxDynamicSharedMemorySize, 4 * 2016 * 8);
        cudaFuncSetAttribute(k_fc1, cudaFuncAttributeMaxDynamicSharedMemorySize, FC1_SMEM);
        attr_done = true;
    }

    const int pairs = (B + 1) / 2;
    k_wt<<<72, 256>>>(c1w, c2w, c3w);
    k_wb<<<(74 * 24 * 64 + 255) / 256, 256>>>(ptw1, cfw1);
    k_wb2<<<32, 256>>>(ptw2);
    k_conv<<<(pairs + 3) / 4, 128, 4 * 2016 * 8>>>(board, c1b, c2b, c3b, qp, B);
    k_fc1<<<B / 128, 256, FC1_SMEM>>>(ptb1, cfb1,
                                      ptb2, ptw3, ptb3, cfw2, cfb2,
                                      (float*)d_out);
}

// round 8
// speedup vs baseline: 1.5921x; 1.2370x over previous
#include <cuda_runtime.h>
#include <math.h>

#define BATCH_MAX 65536
#define FEAT 584
#define FEAT_PAD 592

typedef unsigned long long u64t;

__device__ float g_feats[(size_t)BATCH_MAX * FEAT_PAD + 16]; // +16 pad for float4 tails

// Transposed weight copies (lane-coalesced layouts)
__device__ float g_w1t[27 * 16];        // [tap][co]
__device__ float g_w2t[144 * 32];       // [ci*9+tap][co]
__device__ unsigned g_bfrag[74 * 24 * 64];  // fc1 B, tf32 fragment-major
__device__ unsigned g_w2frag[16 * 8 * 64];  // heads W2, tf32 fragment-major
__device__ unsigned g_w3frag[36 * 8 * 64];  // conv3 W3, tf32 fragment-major

// ---- packed f32x2 helpers -------------------------------------------------
__device__ __forceinline__ float2 ffma2(float2 a, float2 b, float2 c) {
    u64t ua = *(u64t*)&a, ub = *(u64t*)&b, uc = *(u64t*)&c, ud;
    asm("fma.rn.f32x2 %0, %1, %2, %3;" : "=l"(ud) : "l"(ua), "l"(ub), "l"(uc));
    return *(float2*)&ud;
}
__device__ __forceinline__ float2 bcast2(float w) { return make_float2(w, w); }
__device__ __forceinline__ float2 fmax2(float2 a, float2 b) {
    return make_float2(fmaxf(a.x, b.x), fmaxf(a.y, b.y));
}
__device__ __forceinline__ unsigned f2tf32(float v) {
    unsigned o; asm("cvt.rna.tf32.f32 %0, %1;" : "=r"(o) : "f"(v)); return o;
}
#define MMA_TF32(accp, a0, a1, a2, a3, bx, by)                                \
    asm volatile(                                                             \
        "mma.sync.aligned.m16n8k8.row.col.f32.tf32.tf32.f32 "                 \
        "{%0,%1,%2,%3}, {%4,%5,%6,%7}, {%8,%9}, {%0,%1,%2,%3};"               \
        : "+f"((accp)[0]), "+f"((accp)[1]), "+f"((accp)[2]), "+f"((accp)[3])  \
        : "r"(a0), "r"(a1), "r"(a2), "r"(a3), "r"(bx), "r"(by))

// ---------------------------------------------------------------------------
// Kernel 0a: transpose conv1/conv2 weights.
// ---------------------------------------------------------------------------
__global__ void k_wt(const float* __restrict__ w1,
                     const float* __restrict__ w2)
{
    const int i = blockIdx.x * 256 + threadIdx.x;
    if (i < 432)  { int co = i / 27,  r = i - co * 27;  g_w1t[r * 16 + co] = w1[i]; }
    if (i < 4608) { int co = i / 144, r = i - co * 144; g_w2t[r * 32 + co] = w2[i]; }
}

// ---------------------------------------------------------------------------
// Kernel 0b: bake fc1 B = [pt_w1 | cf_w1] into tf32 fragment-major layout.
// ---------------------------------------------------------------------------
__global__ void k_wb(const float* __restrict__ ptw1, const float* __restrict__ cfw1)
{
    const int idx = blockIdx.x * 256 + threadIdx.x;
    if (idx >= 74 * 24 * 64) return;
    const int r = idx & 1;
    const int l = (idx >> 1) & 31;
    const int j = (idx >> 6) % 24;
    const int K8 = idx / (24 * 64);
    const int k = K8 * 8 + r * 4 + (l & 3);
    const int n = j * 8 + (l >> 2);
    float v = 0.f;
    if (k < 584)
        v = (n < 128) ? ptw1[(size_t)k * 128 + n] : cfw1[(size_t)k * 64 + (n - 128)];
    g_bfrag[idx] = f2tf32(v);
}

// ---------------------------------------------------------------------------
// Kernel 0c: bake heads W2 (128x64) into tf32 fragment-major layout.
// ---------------------------------------------------------------------------
__global__ void k_wb2(const float* __restrict__ ptw2)
{
    const int idx = blockIdx.x * 256 + threadIdx.x;
    if (idx >= 16 * 8 * 64) return;
    const int r = idx & 1;
    const int l = (idx >> 1) & 31;
    const int j = (idx >> 6) & 7;
    const int k8 = idx >> 9;
    const int k = k8 * 8 + r * 4 + (l & 3);
    const int n = j * 8 + (l >> 2);
    g_w2frag[idx] = f2tf32(ptw2[(size_t)k * 64 + n]);
}

// ---------------------------------------------------------------------------
// Kernel 0d: bake conv3 W3 (64,32,3,3) into tf32 fragment-major layout.
// B[k=(ci*9+tap)][n=co] = w3[co*288 + k]
// ---------------------------------------------------------------------------
__global__ void k_wb3(const float* __restrict__ w3)
{
    const int idx = blockIdx.x * 256 + threadIdx.x;
    if (idx >= 36 * 8 * 64) return;
    const int r = idx & 1;
    const int l = (idx >> 1) & 31;
    const int j = (idx >> 6) & 7;
    const int k8 = idx >> 9;
    const int k = k8 * 8 + r * 4 + (l & 3);
    const int n = j * 8 + (l >> 2);
    g_w3frag[idx] = f2tf32(w3[(size_t)n * 288 + k]);
}

// ---------------------------------------------------------------------------
// conv2 x-half (unchanged)
// ---------------------------------------------------------------------------
template<int C0, int WIN, int WOUT>
__device__ __forceinline__ void conv2_part(
    const float2* __restrict__ h1p, float2 bias, int lane, float2* __restrict__ pp)
{
    float2 acc[6][WOUT];
    #pragma unroll
    for (int y = 0; y < 6; y++)
        #pragma unroll
        for (int x = 0; x < WOUT; x++) acc[y][x] = bias;

    for (int ci = 0; ci < 16; ci++) {
        float2 w[9];
        #pragma unroll
        for (int i = 0; i < 9; i++) w[i] = bcast2(__ldg(g_w2t + (ci * 9 + i) * 32 + lane));
        const float2* hr = h1p + ci * 64;
        float2 r[3][WIN];
        #pragma unroll
        for (int j = 0; j < WIN; j++) { r[0][j] = hr[C0 + j]; r[1][j] = hr[8 + C0 + j]; }
        #pragma unroll
        for (int y = 0; y < 6; y++) {
            #pragma unroll
            for (int j = 0; j < WIN; j++) r[(y + 2) % 3][j] = hr[(y + 2) * 8 + C0 + j];
            #pragma unroll
            for (int x = 0; x < WOUT; x++) {
                float2 a = acc[y][x];
                a = ffma2(r[(y + 0) % 3][x + 0], w[0], a);
                a = ffma2(r[(y + 0) % 3][x + 1], w[1], a);
                a = ffma2(r[(y + 0) % 3][x + 2], w[2], a);
                a = ffma2(r[(y + 1) % 3][x + 0], w[3], a);
                a = ffma2(r[(y + 1) % 3][x + 1], w[4], a);
                a = ffma2(r[(y + 1) % 3][x + 2], w[5], a);
                a = ffma2(r[(y + 2) % 3][x + 0], w[6], a);
                a = ffma2(r[(y + 2) % 3][x + 1], w[7], a);
                a = ffma2(r[(y + 2) % 3][x + 2], w[8], a);
                acc[y][x] = a;
            }
        }
    }
    #pragma unroll
    for (int py = 0; py < 3; py++)
        #pragma unroll
        for (int pxl = 0; pxl < WOUT / 2; pxl++) {
            float2 m = fmax2(fmax2(acc[2 * py][2 * pxl], acc[2 * py][2 * pxl + 1]),
                             fmax2(acc[2 * py + 1][2 * pxl], acc[2 * py + 1][2 * pxl + 1]));
            m = fmax2(m, make_float2(0.f, 0.f));
            const int px = C0 / 2 + pxl;
            pp[lane * 25 + (py + 1) * 5 + (px + 1)] = m;
        }
}

// ---------------------------------------------------------------------------
// conv3 mma tile: m16 tile mt (rows r=(s,p), 72 valid over the block's 8
// samples), n8 range [n8lo, n8lo+NN). A built on the fly from pp planes via
// the smem off_k table; output staged (bias+relu) into the dead h1p regions
// with stride 65.
// smf float layout per warp region w (stride 4032):
//   [0..384)    inp  (dead post-conv1; warp0's holds off_k[288] + b3s[64])
//   [384..2432) h1p  (dead post-conv2; staging rows 18w..18w+17)
//   [2432..4032) pp  (float2-packed sample pair)
// ---------------------------------------------------------------------------
template<int NN>
__device__ __forceinline__ void conv3_tile(
    float* smf, const int* offk, const float* b3s,
    int mt, int n8lo, int g, int tg, int lane)
{
    const int r1 = mt * 16 + g, r2 = r1 + 8;
    const bool v1 = (r1 < 72), v2 = (r2 < 72);
    int base1 = 0, base2 = 0;
    if (v1) {
        const int s = r1 / 9, p = r1 - 9 * s;
        base1 = (s >> 1) * 4032 + 2432 + (s & 1) + 2 * ((p / 3) * 5 + (p % 3));
    }
    if (v2) {
        const int s = r2 / 9, p = r2 - 9 * s;
        base2 = (s >> 1) * 4032 + 2432 + (s & 1) + 2 * ((p / 3) * 5 + (p % 3));
    }

    float acc[NN][4];
    #pragma unroll
    for (int j = 0; j < NN; j++)
        #pragma unroll
        for (int q = 0; q < 4; q++) acc[j][q] = 0.f;

    for (int k8 = 0; k8 < 36; k8++) {
        const int oa = offk[k8 * 8 + tg] * 2;
        const int oc = offk[k8 * 8 + tg + 4] * 2;
        const unsigned a0 = v1 ? f2tf32(smf[base1 + oa]) : 0u;
        const unsigned a1 = v2 ? f2tf32(smf[base2 + oa]) : 0u;
        const unsigned a2 = v1 ? f2tf32(smf[base1 + oc]) : 0u;
        const unsigned a3 = v2 ? f2tf32(smf[base2 + oc]) : 0u;
        #pragma unroll
        for (int j = 0; j < NN; j++) {
            const uint2 b = __ldg((const uint2*)g_w3frag + (k8 * 8 + n8lo + j) * 32 + lane);
            MMA_TF32(acc[j], a0, a1, a2, a3, b.x, b.y);
        }
    }
    #pragma unroll
    for (int j = 0; j < NN; j++)
        #pragma unroll
        for (int q = 0; q < 4; q++) {
            const int n = (n8lo + j) * 8 + tg * 2 + (q & 1);
            const int r = (q < 2) ? r1 : r2;
            if (r < 72)
                smf[(r / 18) * 4032 + 384 + (r % 18) * 65 + n] =
                    fmaxf(acc[j][q] + b3s[n], 0.f);
        }
}

// ---------------------------------------------------------------------------
// Kernel 1: conv pipeline + quantum sim. conv1/conv2 scalar per-warp (2
// samples packed f32x2); conv3 block-cooperative tf32 mma over 8 samples.
// ---------------------------------------------------------------------------
__global__ __launch_bounds__(128) void k_conv(
    const float* __restrict__ board,
    const float* __restrict__ b1,
    const float* __restrict__ b2,
    const float* __restrict__ b3,
    const float* __restrict__ qp, int nsamp)
{
    extern __shared__ float2 smc[];
    float* smf = (float*)smc;
    const int tid = threadIdx.x;
    const int warp = tid >> 5, lane = tid & 31;
    const int pidx = blockIdx.x * 4 + warp;
    const int s0 = 2 * pidx;
    const bool active = (s0 < nsamp);
    const bool has2 = (s0 + 1 < nsamp);

    float2* inp = smc + (size_t)warp * 2016;
    float2* h1p = inp + 192;
    float2* pp  = inp + 1216;

    // ---- zero per-warp smem (unconditional: inactive warps' pp must be 0)
    for (int i = lane; i < 2016; i += 32) inp[i] = make_float2(0.f, 0.f);
    __syncwarp();

    if (active) {
        const float* bs0 = board + (size_t)s0 * 108;
        const float* bs1 = has2 ? bs0 + 108 : bs0;

        for (int i = lane; i < 108; i += 32) {
            int ci = i / 36, r = i - ci * 36;
            int y = r / 6, x = r - y * 6;
            inp[ci * 64 + (y + 1) * 8 + (x + 1)] = make_float2(bs0[i], bs1[i]);
        }

        if (lane < 16) {   // quantum + pad-zero
            const int smp = lane >> 3, qb = lane & 7;
            const int sg = s0 + smp;
            if (sg < nsamp) {
                const float* bq = board + (size_t)sg * 108;
                float xv = bq[qb], xn = bq[(qb + 1) & 7];
                float q = 0.f;
                #pragma unroll
                for (int l = 0; l < 3; l++) {
                    float r0 = __ldg(qp + (l * 8 + qb) * 3 + 0);
                    float r1 = __ldg(qp + (l * 8 + qb) * 3 + 1);
                    float r2 = __ldg(qp + (l * 8 + qb) * 3 + 2);
                    q = sinf(r0 * xv) * cosf(r1 * xn) + tanhf(r2 * q);
                }
                g_feats[(size_t)sg * FEAT_PAD + 576 + qb] = q;
                g_feats[(size_t)sg * FEAT_PAD + 584 + qb] = 0.f;
            }
        }
        __syncwarp();

        {   // conv1
            const int co = lane & 15, half = lane >> 4;
            float2 w[27];
            #pragma unroll
            for (int i = 0; i < 27; i++) w[i] = bcast2(__ldg(g_w1t + i * 16 + co));
            const float2 bias = bcast2(__ldg(b1 + co));
            #pragma unroll
            for (int p = 0; p < 18; p++) {
                const int yy = half * 3 + p / 6;
                const int xx = p % 6;
                const int y8 = yy * 8;
                float2 a = bias;
                #pragma unroll
                for (int ci = 0; ci < 3; ci++)
                    #pragma unroll
                    for (int ky = 0; ky < 3; ky++)
                        #pragma unroll
                        for (int kx = 0; kx < 3; kx++)
                            a = ffma2(inp[ci * 64 + y8 + ky * 8 + xx + kx],
                                      w[ci * 9 + ky * 3 + kx], a);
                h1p[co * 64 + y8 + 8 + xx + 1] = fmax2(a, make_float2(0.f, 0.f));
            }
        }
        __syncwarp();

        {   // conv2 (+relu+pool)
            const float2 bias2 = bcast2(__ldg(b2 + lane));
            conv2_part<0, 6, 4>(h1p, bias2, lane, pp);
            conv2_part<4, 4, 2>(h1p, bias2, lane, pp);
        }
    }
    __syncthreads();

    // ---- fill conv3 tables into warp0's dead inp region
    for (int i = tid; i < 288; i += 128) {
        const int ci = i / 9, tap = i - ci * 9;
        ((int*)smf)[i] = ci * 25 + (tap / 3) * 5 + (tap % 3);
    }
    if (tid < 64) smf[288 + tid] = __ldg(b3 + tid);
    __syncthreads();

    // ---- conv3 via mma: warp w does m-tile w (all 8 n8) + tile 4 (2 n8)
    {
        const int g = lane >> 2, tg = lane & 3;
        const int* offk = (const int*)smf;
        const float* b3s = smf + 288;
        conv3_tile<8>(smf, offk, b3s, warp, 0, g, tg, lane);
        conv3_tile<2>(smf, offk, b3s, 4, 2 * warp, g, tg, lane);
    }
    __syncthreads();

    // ---- copy staged conv3 output to g_feats (coalesced stores)
    {
        const int s = tid >> 4, li = tid & 15;
        const int sg = blockIdx.x * 8 + s;
        if (sg < nsamp) {
            float* f = g_feats + (size_t)sg * FEAT_PAD;
            for (int i = li; i < 576; i += 16) {
                const int co = i / 9, p = i - 9 * co;
                const int r = s * 9 + p;
                f[i] = smf[(r / 18) * 4032 + 384 + (r % 18) * 65 + co];
            }
        }
    }
}

// ---------------------------------------------------------------------------
// Kernel 2 (fused, all-tensor-core): unchanged from round 7.
// ---------------------------------------------------------------------------
#define FC1_SMEM (25536 * 4)

__global__ __launch_bounds__(256) void k_fc1(
    const float* __restrict__ ptb1, const float* __restrict__ cfb1,
    const float* __restrict__ ptb2,
    const float* __restrict__ ptw3, const float* __restrict__ ptb3,
    const float* __restrict__ cfw2, const float* __restrict__ cfb2,
    float* __restrict__ out)
{
    extern __shared__ float sfc[];
    unsigned* A_s = (unsigned*)sfc;            // 2048
    unsigned* B_s = (unsigned*)(sfc + 2048);   // 3072
    float* C1s    = sfc;                       // 25088 (post-GEMM alias)
    float* BiasS  = sfc + 25088;               // 192
    float* W3s    = sfc + 25280;               // 128
    float* CW2s   = sfc + 25408;               // 64
    float* B2s    = sfc + 25472;               // 64

    const int t = threadIdx.x;
    const int m0 = blockIdx.x * 128;
    const int warp = t >> 5, lane = t & 31;
    const int wm = warp >> 1, wn = warp & 1;
    const int g = lane >> 2, tg = lane & 3;

    if (t < 192) BiasS[t] = (t < 128) ? __ldg(ptb1 + t) : __ldg(cfb1 + t - 128);
    if (t < 128) W3s[t] = __ldg(ptw3 + t);
    if (t < 64)  { CW2s[t] = __ldg(cfw2 + t); B2s[t] = __ldg(ptb2 + t); }

    float acc[2][12][4];
    #pragma unroll
    for (int i = 0; i < 2; i++)
        #pragma unroll
        for (int j = 0; j < 12; j++)
            #pragma unroll
            for (int r = 0; r < 4; r++) acc[i][j][r] = 0.f;

    const int am = t >> 1;
    const int kcA = t & 1;
    const int rA = am & 15, mtA = am >> 4;
    const int baseA = ((kcA * 8 + mtA) * 32 + (rA & 7) * 4) * 4 + (rA >> 3);
    const float* arow = g_feats + (size_t)(m0 + am) * FEAT_PAD + kcA * 8;

    float4 av0 = *(const float4*)(arow);
    float4 av1 = *(const float4*)(arow + 4);
    uint4 bv0 = *(const uint4*)(g_bfrag + t * 12);
    uint4 bv1 = *(const uint4*)(g_bfrag + t * 12 + 4);
    uint4 bv2 = *(const uint4*)(g_bfrag + t * 12 + 8);

    for (int it = 0; it < 37; ++it) {
        A_s[baseA + 0 * 4 + 0] = f2tf32(av0.x);
        A_s[baseA + 1 * 4 + 0] = f2tf32(av0.y);
        A_s[baseA + 2 * 4 + 0] = f2tf32(av0.z);
        A_s[baseA + 3 * 4 + 0] = f2tf32(av0.w);
        A_s[baseA + 0 * 4 + 2] = f2tf32(av1.x);
        A_s[baseA + 1 * 4 + 2] = f2tf32(av1.y);
        A_s[baseA + 2 * 4 + 2] = f2tf32(av1.z);
        A_s[baseA + 3 * 4 + 2] = f2tf32(av1.w);
        *(uint4*)(B_s + t * 12)     = bv0;
        *(uint4*)(B_s + t * 12 + 4) = bv1;
        *(uint4*)(B_s + t * 12 + 8) = bv2;
        __syncthreads();
        if (it < 36) {
            av0 = *(const float4*)(arow + (it + 1) * 16);
            av1 = *(const float4*)(arow + (it + 1) * 16 + 4);
            const unsigned* bsrc = g_bfrag + (it + 1) * 3072 + t * 12;
            bv0 = *(const uint4*)(bsrc);
            bv1 = *(const uint4*)(bsrc + 4);
            bv2 = *(const uint4*)(bsrc + 8);
        }
        #pragma unroll
        for (int kc = 0; kc < 2; kc++) {
            unsigned af[2][4];
            #pragma unroll
            for (int i = 0; i < 2; i++) {
                const uint4 v = *(const uint4*)(A_s + ((kc * 8 + wm * 2 + i) * 32 + lane) * 4);
                af[i][0] = v.x; af[i][1] = v.y; af[i][2] = v.z; af[i][3] = v.w;
            }
            #pragma unroll
            for (int j = 0; j < 12; j++) {
                const uint2 b = *(const uint2*)(B_s + ((kc * 24 + wn * 12 + j) * 32 + lane) * 2);
                #pragma unroll
                for (int i = 0; i < 2; i++)
                    MMA_TF32(acc[i][j], af[i][0], af[i][1], af[i][2], af[i][3], b.x, b.y);
            }
        }
        __syncthreads();
    }

    #pragma unroll
    for (int i = 0; i < 2; i++)
        #pragma unroll
        for (int j = 0; j < 12; j++)
            #pragma unroll
            for (int r = 0; r < 4; r++) {
                const int m = wm * 32 + i * 16 + ((r >> 1) << 3) + g;
                const int n = wn * 96 + j * 8 + tg * 2 + (r & 1);
                C1s[m * 196 + n] = fmaxf(acc[i][j][r] + BiasS[n], 0.f);
            }
    __syncthreads();

    {
        const int base = warp * 16;
        float hacc[8][4];
        #pragma unroll
        for (int j = 0; j < 8; j++)
            #pragma unroll
            for (int r = 0; r < 4; r++) hacc[j][r] = 0.f;

        #pragma unroll 4
        for (int k8 = 0; k8 < 16; k8++) {
            const float* cA = C1s + base * 196 + k8 * 8;
            const unsigned a0 = f2tf32(cA[g * 196 + tg]);
            const unsigned a1 = f2tf32(cA[(g + 8) * 196 + tg]);
            const unsigned a2 = f2tf32(cA[g * 196 + tg + 4]);
            const unsigned a3 = f2tf32(cA[(g + 8) * 196 + tg + 4]);
            #pragma unroll
            for (int j = 0; j < 8; j++) {
                const uint2 b = __ldg((const uint2*)g_w2frag + (k8 * 8 + j) * 32 + lane);
                MMA_TF32(hacc[j], a0, a1, a2, a3, b.x, b.y);
            }
        }

        float l0g = 0.f, l1g = 0.f, l0h = 0.f, l1h = 0.f;
        #pragma unroll
        for (int j = 0; j < 8; j++)
            #pragma unroll
            for (int r = 0; r < 4; r++) {
                const int n = j * 8 + tg * 2 + (r & 1);
                const float v = fmaxf(hacc[j][r] + B2s[n], 0.f);
                const float w30 = W3s[n * 2], w31 = W3s[n * 2 + 1];
                if (r < 2) { l0g = fmaf(v, w30, l0g); l1g = fmaf(v, w31, l1g); }
                else       { l0h = fmaf(v, w30, l0h); l1h = fmaf(v, w31, l1h); }
            }
        #pragma unroll
        for (int off = 1; off <= 2; off <<= 1) {
            l0g += __shfl_xor_sync(0xffffffffu, l0g, off);
            l1g += __shfl_xor_sync(0xffffffffu, l1g, off);
            l0h += __shfl_xor_sync(0xffffffffu, l0h, off);
            l1h += __shfl_xor_sync(0xffffffffu, l1h, off);
        }
        if (tg == 0) {
            const float b30 = __ldg(ptb3 + 0), b31 = __ldg(ptb3 + 1);
            {
                const float l0 = l0g + b30, l1 = l1g + b31;
                const float mx = fmaxf(l0, l1);
                const float e0 = expf(l0 - mx), e1 = expf(l1 - mx);
                const float inv = 1.f / (e0 + e1);
                out[(size_t)(m0 + base + g) * 3 + 0] = e0 * inv;
                out[(size_t)(m0 + base + g) * 3 + 1] = e1 * inv;
            }
            {
                const float l0 = l0h + b30, l1 = l1h + b31;
                const float mx = fmaxf(l0, l1);
                const float e0 = expf(l0 - mx), e1 = expf(l1 - mx);
                const float inv = 1.f / (e0 + e1);
                out[(size_t)(m0 + base + g + 8) * 3 + 0] = e0 * inv;
                out[(size_t)(m0 + base + g + 8) * 3 + 1] = e1 * inv;
            }
        }

        for (int i = 0; i < 16; i++) {
            const int ml = base + i;
            const float* c1 = C1s + ml * 196;
            float cc = c1[128 + lane] * CW2s[lane] + c1[160 + lane] * CW2s[lane + 32];
            #pragma unroll
            for (int off = 16; off; off >>= 1)
                cc += __shfl_xor_sync(0xffffffffu, cc, off);
            if (lane == 0)
                out[(size_t)(m0 + ml) * 3 + 2] =
                    1.f / (1.f + expf(-(cc + __ldg(cfb2))));
        }
    }
}

// ---------------------------------------------------------------------------
extern "C" void kernel_launch(void* const* d_in, const int* in_sizes, int n_in,
                              void* d_out, int out_size)
{
    const float* board = (const float*)d_in[0];
    // d_in[1] = target_positions (int64) — mathematically unused
    const float* c1w = (const float*)d_in[2];  const float* c1b = (const float*)d_in[3];
    const float* c2w = (const float*)d_in[4];  const float* c2b = (const float*)d_in[5];
    const float* c3w = (const float*)d_in[6];  const float* c3b = (const float*)d_in[7];
    const float* qp  = (const float*)d_in[8];
    const float* ptw1 = (const float*)d_in[9];  const float* ptb1 = (const float*)d_in[10];
    const float* ptw2 = (const float*)d_in[11]; const float* ptb2 = (const float*)d_in[12];
    const float* ptw3 = (const float*)d_in[13]; const float* ptb3 = (const float*)d_in[14];
    const float* cfw1 = (const float*)d_in[15]; const float* cfb1 = (const float*)d_in[16];
    const float* cfw2 = (const float*)d_in[17]; const float* cfb2 = (const float*)d_in[18];

    int B = in_sizes[0] / 108;
    if (B > BATCH_MAX) B = BATCH_MAX;

    static bool attr_done = false;
    if (!attr_done) {
        cudaFuncSetAttribute(k_conv, cudaFuncAttributeMaxDynamicSharedMemorySize, 4 * 2016 * 8);
        cudaFuncSetAttribute(k_fc1, cudaFuncAttributeMaxDynamicSharedMemorySize, FC1_SMEM);
        attr_done = true;
    }

    const int pairs = (B + 1) / 2;
    k_wt<<<18, 256>>>(c1w, c2w);
    k_wb<<<(74 * 24 * 64 + 255) / 256, 256>>>(ptw1, cfw1);
    k_wb2<<<32, 256>>>(ptw2);
    k_wb3<<<72, 256>>>(c3w);
    k_conv<<<(pairs + 3) / 4, 128, 4 * 2016 * 8>>>(board, c1b, c2b, c3b, qp, B);
    k_fc1<<<B / 128, 256, FC1_SMEM>>>(ptb1, cfb1,
                                      ptb2, ptw3, ptb3, cfw2, cfb2,
                                      (float*)d_out);
}

// round 9
// speedup vs baseline: 1.7926x; 1.1260x over previous
#include <cuda_runtime.h>
#include <math.h>

#define BATCH_MAX 65536
#define FEAT 584
#define FEAT_PAD 592

typedef unsigned long long u64t;

__device__ float g_feats[(size_t)BATCH_MAX * FEAT_PAD + 16]; // +16 pad for float4 tails

// Weight copies
__device__ float g_w1t[27 * 16];            // [tap][co]
__device__ unsigned g_bfrag[74 * 24 * 64];  // fc1 B, tf32 fragment-major
__device__ unsigned g_w2frag[16 * 8 * 64];  // heads W2, tf32 fragment-major
__device__ unsigned g_w3frag[36 * 8 * 64];  // conv3 W3, tf32 fragment-major
__device__ unsigned g_w2cfrag[18 * 4 * 64]; // conv2 W2, tf32 fragment-major

// ---- packed f32x2 helpers -------------------------------------------------
__device__ __forceinline__ float2 ffma2(float2 a, float2 b, float2 c) {
    u64t ua = *(u64t*)&a, ub = *(u64t*)&b, uc = *(u64t*)&c, ud;
    asm("fma.rn.f32x2 %0, %1, %2, %3;" : "=l"(ud) : "l"(ua), "l"(ub), "l"(uc));
    return *(float2*)&ud;
}
__device__ __forceinline__ float2 bcast2(float w) { return make_float2(w, w); }
__device__ __forceinline__ float2 fmax2(float2 a, float2 b) {
    return make_float2(fmaxf(a.x, b.x), fmaxf(a.y, b.y));
}
__device__ __forceinline__ unsigned f2tf32(float v) {
    unsigned o; asm("cvt.rna.tf32.f32 %0, %1;" : "=r"(o) : "f"(v)); return o;
}
#define MMA_TF32(accp, a0, a1, a2, a3, bx, by)                                \
    asm volatile(                                                             \
        "mma.sync.aligned.m16n8k8.row.col.f32.tf32.tf32.f32 "                 \
        "{%0,%1,%2,%3}, {%4,%5,%6,%7}, {%8,%9}, {%0,%1,%2,%3};"               \
        : "+f"((accp)[0]), "+f"((accp)[1]), "+f"((accp)[2]), "+f"((accp)[3])  \
        : "r"(a0), "r"(a1), "r"(a2), "r"(a3), "r"(bx), "r"(by))

// ---------------------------------------------------------------------------
// Kernel 0a: transpose conv1 weights.
// ---------------------------------------------------------------------------
__global__ void k_wt(const float* __restrict__ w1)
{
    const int i = blockIdx.x * 256 + threadIdx.x;
    if (i < 432) { int co = i / 27, r = i - co * 27; g_w1t[r * 16 + co] = w1[i]; }
}

// ---------------------------------------------------------------------------
// Kernel 0b: bake fc1 B = [pt_w1 | cf_w1] into tf32 fragment-major layout.
// ---------------------------------------------------------------------------
__global__ void k_wb(const float* __restrict__ ptw1, const float* __restrict__ cfw1)
{
    const int idx = blockIdx.x * 256 + threadIdx.x;
    if (idx >= 74 * 24 * 64) return;
    const int r = idx & 1;
    const int l = (idx >> 1) & 31;
    const int j = (idx >> 6) % 24;
    const int K8 = idx / (24 * 64);
    const int k = K8 * 8 + r * 4 + (l & 3);
    const int n = j * 8 + (l >> 2);
    float v = 0.f;
    if (k < 584)
        v = (n < 128) ? ptw1[(size_t)k * 128 + n] : cfw1[(size_t)k * 64 + (n - 128)];
    g_bfrag[idx] = f2tf32(v);
}

// ---------------------------------------------------------------------------
// Kernel 0c: bake heads W2 (128x64) into tf32 fragment-major layout.
// ---------------------------------------------------------------------------
__global__ void k_wb2(const float* __restrict__ ptw2)
{
    const int idx = blockIdx.x * 256 + threadIdx.x;
    if (idx >= 16 * 8 * 64) return;
    const int r = idx & 1;
    const int l = (idx >> 1) & 31;
    const int j = (idx >> 6) & 7;
    const int k8 = idx >> 9;
    const int k = k8 * 8 + r * 4 + (l & 3);
    const int n = j * 8 + (l >> 2);
    g_w2frag[idx] = f2tf32(ptw2[(size_t)k * 64 + n]);
}

// ---------------------------------------------------------------------------
// Kernel 0d: bake conv3 W3 (64,32,3,3): B[k=(ci*9+tap)][n=co] = w3[co*288+k]
// ---------------------------------------------------------------------------
__global__ void k_wb3(const float* __restrict__ w3)
{
    const int idx = blockIdx.x * 256 + threadIdx.x;
    if (idx >= 36 * 8 * 64) return;
    const int r = idx & 1;
    const int l = (idx >> 1) & 31;
    const int j = (idx >> 6) & 7;
    const int k8 = idx >> 9;
    const int k = k8 * 8 + r * 4 + (l & 3);
    const int n = j * 8 + (l >> 2);
    g_w3frag[idx] = f2tf32(w3[(size_t)n * 288 + k]);
}

// ---------------------------------------------------------------------------
// Kernel 0e: bake conv2 W2 (32,16,3,3): B[k=(ci*9+tap)][n=co] = w2[co*144+k]
// ---------------------------------------------------------------------------
__global__ void k_wb2c(const float* __restrict__ w2)
{
    const int idx = blockIdx.x * 256 + threadIdx.x;
    if (idx >= 18 * 4 * 64) return;
    const int r = idx & 1;
    const int l = (idx >> 1) & 31;
    const int j = (idx >> 6) & 3;
    const int k8 = idx >> 8;
    const int k = k8 * 8 + r * 4 + (l & 3);
    const int n = j * 8 + (l >> 2);
    g_w2cfrag[idx] = f2tf32(w2[(size_t)n * 144 + k]);
}

// ---------------------------------------------------------------------------
// conv2 row mapping: r = s*36 + q*4 + sub (q = pool group 0..8, sub = 2x2 pos)
// -> float offset of h1p pixel (py, px) for that sample.
// ---------------------------------------------------------------------------
__device__ __forceinline__ int c2_rowbase(int r)
{
    const int s = r / 36, rem = r - 36 * s;
    const int q = rem >> 2, sub = rem & 3;
    const int qy = q / 3, qx = q - 3 * qy;
    const int py = 2 * qy + (sub >> 1);
    const int px = 2 * qx + (sub & 1);
    return (s >> 1) * 4032 + 384 + (s & 1) + 2 * (py * 8 + px);
}

// ---------------------------------------------------------------------------
// conv2 mma tile: m16 tile mt over rows (s,q,sub), K=144, N=32. Fused
// relu+2x2 maxpool in the fragment epilogue (shfl-max over the 4 consecutive
// rows of each pool group), writes packed pp planes (conv3 input).
// ---------------------------------------------------------------------------
__device__ __forceinline__ void conv2_tile(
    float* smf, const int* offk2, const float* b2s,
    int mt, int g, int tg, int lane)
{
    const int r1 = mt * 16 + g, r2 = r1 + 8;
    const int base1 = c2_rowbase(r1), base2 = c2_rowbase(r2);

    float acc[4][4];
    #pragma unroll
    for (int j = 0; j < 4; j++)
        #pragma unroll
        for (int q = 0; q < 4; q++) acc[j][q] = 0.f;

    for (int k8 = 0; k8 < 18; k8++) {
        const int oa = offk2[k8 * 8 + tg];
        const int oc = offk2[k8 * 8 + tg + 4];
        const unsigned a0 = f2tf32(smf[base1 + oa]);
        const unsigned a1 = f2tf32(smf[base2 + oa]);
        const unsigned a2 = f2tf32(smf[base1 + oc]);
        const unsigned a3 = f2tf32(smf[base2 + oc]);
        #pragma unroll
        for (int j = 0; j < 4; j++) {
            const uint2 b = __ldg((const uint2*)g_w2cfrag + (k8 * 4 + j) * 32 + lane);
            MMA_TF32(acc[j], a0, a1, a2, a3, b.x, b.y);
        }
    }

    // maxpool across the 4 consecutive rows of each pool group (lanes g^1, g^2)
    #pragma unroll
    for (int j = 0; j < 4; j++)
        #pragma unroll
        for (int q = 0; q < 4; q++) {
            float v = acc[j][q];
            v = fmaxf(v, __shfl_xor_sync(0xffffffffu, v, 4));
            v = fmaxf(v, __shfl_xor_sync(0xffffffffu, v, 8));
            acc[j][q] = v;
        }
    if ((g & 3) == 0) {
        #pragma unroll
        for (int j = 0; j < 4; j++)
            #pragma unroll
            for (int q = 0; q < 4; q++) {
                const int n = j * 8 + tg * 2 + (q & 1);
                const int r = (q < 2) ? r1 : r2;
                const int gq = r >> 2;
                const int s = gq / 9, qp = gq - 9 * s;
                const int py = qp / 3, px = qp - 3 * py;
                smf[(s >> 1) * 4032 + 2432 + (s & 1)
                    + 2 * (n * 25 + (py + 1) * 5 + (px + 1))]
                    = fmaxf(acc[j][q] + b2s[n], 0.f);
            }
    }
}

// ---------------------------------------------------------------------------
// conv3 mma tile (unchanged from round 8)
// ---------------------------------------------------------------------------
template<int NN>
__device__ __forceinline__ void conv3_tile(
    float* smf, const int* offk, const float* b3s,
    int mt, int n8lo, int g, int tg, int lane)
{
    const int r1 = mt * 16 + g, r2 = r1 + 8;
    const bool v1 = (r1 < 72), v2 = (r2 < 72);
    int base1 = 0, base2 = 0;
    if (v1) {
        const int s = r1 / 9, p = r1 - 9 * s;
        base1 = (s >> 1) * 4032 + 2432 + (s & 1) + 2 * ((p / 3) * 5 + (p % 3));
    }
    if (v2) {
        const int s = r2 / 9, p = r2 - 9 * s;
        base2 = (s >> 1) * 4032 + 2432 + (s & 1) + 2 * ((p / 3) * 5 + (p % 3));
    }

    float acc[NN][4];
    #pragma unroll
    for (int j = 0; j < NN; j++)
        #pragma unroll
        for (int q = 0; q < 4; q++) acc[j][q] = 0.f;

    for (int k8 = 0; k8 < 36; k8++) {
        const int oa = offk[k8 * 8 + tg] * 2;
        const int oc = offk[k8 * 8 + tg + 4] * 2;
        const unsigned a0 = v1 ? f2tf32(smf[base1 + oa]) : 0u;
        const unsigned a1 = v2 ? f2tf32(smf[base2 + oa]) : 0u;
        const unsigned a2 = v1 ? f2tf32(smf[base1 + oc]) : 0u;
        const unsigned a3 = v2 ? f2tf32(smf[base2 + oc]) : 0u;
        #pragma unroll
        for (int j = 0; j < NN; j++) {
            const uint2 b = __ldg((const uint2*)g_w3frag + (k8 * 8 + n8lo + j) * 32 + lane);
            MMA_TF32(acc[j], a0, a1, a2, a3, b.x, b.y);
        }
    }
    #pragma unroll
    for (int j = 0; j < NN; j++)
        #pragma unroll
        for (int q = 0; q < 4; q++) {
            const int n = (n8lo + j) * 8 + tg * 2 + (q & 1);
            const int r = (q < 2) ? r1 : r2;
            if (r < 72)
                smf[(r / 18) * 4032 + 384 + (r % 18) * 65 + n] =
                    fmaxf(acc[j][q] + b3s[n], 0.f);
        }
}

// ---------------------------------------------------------------------------
// Kernel 1: conv pipeline + quantum sim. conv1 scalar per-warp (2 samples
// packed f32x2); conv2 and conv3 block-cooperative tf32 mma over 8 samples.
// ---------------------------------------------------------------------------
__global__ __launch_bounds__(128) void k_conv(
    const float* __restrict__ board,
    const float* __restrict__ b1,
    const float* __restrict__ b2,
    const float* __restrict__ b3,
    const float* __restrict__ qp, int nsamp)
{
    extern __shared__ float2 smc[];
    float* smf = (float*)smc;
    const int tid = threadIdx.x;
    const int warp = tid >> 5, lane = tid & 31;
    const int pidx = blockIdx.x * 4 + warp;
    const int s0 = 2 * pidx;
    const bool active = (s0 < nsamp);
    const bool has2 = (s0 + 1 < nsamp);

    float2* inp = smc + (size_t)warp * 2016;
    float2* h1p = inp + 192;

    // ---- zero per-warp smem (unconditional: inactive warps' planes must be 0)
    for (int i = lane; i < 2016; i += 32) inp[i] = make_float2(0.f, 0.f);
    __syncwarp();

    if (active) {
        const float* bs0 = board + (size_t)s0 * 108;
        const float* bs1 = has2 ? bs0 + 108 : bs0;

        for (int i = lane; i < 108; i += 32) {
            int ci = i / 36, r = i - ci * 36;
            int y = r / 6, x = r - y * 6;
            inp[ci * 64 + (y + 1) * 8 + (x + 1)] = make_float2(bs0[i], bs1[i]);
        }

        if (lane < 16) {   // quantum + pad-zero
            const int smp = lane >> 3, qb = lane & 7;
            const int sg = s0 + smp;
            if (sg < nsamp) {
                const float* bq = board + (size_t)sg * 108;
                float xv = bq[qb], xn = bq[(qb + 1) & 7];
                float q = 0.f;
                #pragma unroll
                for (int l = 0; l < 3; l++) {
                    float r0 = __ldg(qp + (l * 8 + qb) * 3 + 0);
                    float r1 = __ldg(qp + (l * 8 + qb) * 3 + 1);
                    float r2 = __ldg(qp + (l * 8 + qb) * 3 + 2);
                    q = sinf(r0 * xv) * cosf(r1 * xn) + tanhf(r2 * q);
                }
                g_feats[(size_t)sg * FEAT_PAD + 576 + qb] = q;
                g_feats[(size_t)sg * FEAT_PAD + 584 + qb] = 0.f;
            }
        }
        __syncwarp();

        {   // conv1
            const int co = lane & 15, half = lane >> 4;
            float2 w[27];
            #pragma unroll
            for (int i = 0; i < 27; i++) w[i] = bcast2(__ldg(g_w1t + i * 16 + co));
            const float2 bias = bcast2(__ldg(b1 + co));
            #pragma unroll
            for (int p = 0; p < 18; p++) {
                const int yy = half * 3 + p / 6;
                const int xx = p % 6;
                const int y8 = yy * 8;
                float2 a = bias;
                #pragma unroll
                for (int ci = 0; ci < 3; ci++)
                    #pragma unroll
                    for (int ky = 0; ky < 3; ky++)
                        #pragma unroll
                        for (int kx = 0; kx < 3; kx++)
                            a = ffma2(inp[ci * 64 + y8 + ky * 8 + xx + kx],
                                      w[ci * 9 + ky * 3 + kx], a);
                h1p[co * 64 + y8 + 8 + xx + 1] = fmax2(a, make_float2(0.f, 0.f));
            }
        }
    }
    __syncthreads();

    // ---- fill tables into dead inp regions (warp0: conv3; warp1: conv2)
    for (int i = tid; i < 288; i += 128) {
        const int ci = i / 9, tap = i - ci * 9;
        ((int*)smf)[i] = ci * 25 + (tap / 3) * 5 + (tap % 3);
    }
    for (int i = tid; i < 144; i += 128) {
        const int ci = i / 9, tap = i - ci * 9;
        ((int*)(smf + 4032))[i] = 2 * (ci * 64 + (tap / 3) * 8 + (tap % 3));
    }
    if (tid < 64) smf[288 + tid] = __ldg(b3 + tid);
    if (tid < 32) smf[4200 + tid] = __ldg(b2 + tid);
    __syncthreads();

    // ---- conv2 via mma (+fused relu+pool): 18 m-tiles over the block
    {
        const int g = lane >> 2, tg = lane & 3;
        const int* offk2 = (const int*)(smf + 4032);
        const float* b2s = smf + 4200;
        conv2_tile(smf, offk2, b2s, warp,      g, tg, lane);
        conv2_tile(smf, offk2, b2s, warp + 4,  g, tg, lane);
        conv2_tile(smf, offk2, b2s, warp + 8,  g, tg, lane);
        conv2_tile(smf, offk2, b2s, warp + 12, g, tg, lane);
        if (warp < 2) conv2_tile(smf, offk2, b2s, 16 + warp, g, tg, lane);
    }
    __syncthreads();

    // ---- conv3 via mma: warp w does m-tile w (all 8 n8) + tile 4 (2 n8)
    {
        const int g = lane >> 2, tg = lane & 3;
        const int* offk = (const int*)smf;
        const float* b3s = smf + 288;
        conv3_tile<8>(smf, offk, b3s, warp, 0, g, tg, lane);
        conv3_tile<2>(smf, offk, b3s, 4, 2 * warp, g, tg, lane);
    }
    __syncthreads();

    // ---- copy staged conv3 output to g_feats (coalesced stores)
    {
        const int s = tid >> 4, li = tid & 15;
        const int sg = blockIdx.x * 8 + s;
        if (sg < nsamp) {
            float* f = g_feats + (size_t)sg * FEAT_PAD;
            for (int i = li; i < 576; i += 16) {
                const int co = i / 9, p = i - 9 * co;
                const int r = s * 9 + p;
                f[i] = smf[(r / 18) * 4032 + 384 + (r % 18) * 65 + co];
            }
        }
    }
}

// ---------------------------------------------------------------------------
// Kernel 2 (fused, all-tensor-core): unchanged from round 8.
// ---------------------------------------------------------------------------
#define FC1_SMEM (25536 * 4)

__global__ __launch_bounds__(256) void k_fc1(
    const float* __restrict__ ptb1, const float* __restrict__ cfb1,
    const float* __restrict__ ptb2,
    const float* __restrict__ ptw3, const float* __restrict__ ptb3,
    const float* __restrict__ cfw2, const float* __restrict__ cfb2,
    float* __restrict__ out)
{
    extern __shared__ float sfc[];
    unsigned* A_s = (unsigned*)sfc;            // 2048
    unsigned* B_s = (unsigned*)(sfc + 2048);   // 3072
    float* C1s    = sfc;                       // 25088 (post-GEMM alias)
    float* BiasS  = sfc + 25088;               // 192
    float* W3s    = sfc + 25280;               // 128
    float* CW2s   = sfc + 25408;               // 64
    float* B2s    = sfc + 25472;               // 64

    const int t = threadIdx.x;
    const int m0 = blockIdx.x * 128;
    const int warp = t >> 5, lane = t & 31;
    const int wm = warp >> 1, wn = warp & 1;
    const int g = lane >> 2, tg = lane & 3;

    if (t < 192) BiasS[t] = (t < 128) ? __ldg(ptb1 + t) : __ldg(cfb1 + t - 128);
    if (t < 128) W3s[t] = __ldg(ptw3 + t);
    if (t < 64)  { CW2s[t] = __ldg(cfw2 + t); B2s[t] = __ldg(ptb2 + t); }

    float acc[2][12][4];
    #pragma unroll
    for (int i = 0; i < 2; i++)
        #pragma unroll
        for (int j = 0; j < 12; j++)
            #pragma unroll
            for (int r = 0; r < 4; r++) acc[i][j][r] = 0.f;

    const int am = t >> 1;
    const int kcA = t & 1;
    const int rA = am & 15, mtA = am >> 4;
    const int baseA = ((kcA * 8 + mtA) * 32 + (rA & 7) * 4) * 4 + (rA >> 3);
    const float* arow = g_feats + (size_t)(m0 + am) * FEAT_PAD + kcA * 8;

    float4 av0 = *(const float4*)(arow);
    float4 av1 = *(const float4*)(arow + 4);
    uint4 bv0 = *(const uint4*)(g_bfrag + t * 12);
    uint4 bv1 = *(const uint4*)(g_bfrag + t * 12 + 4);
    uint4 bv2 = *(const uint4*)(g_bfrag + t * 12 + 8);

    for (int it = 0; it < 37; ++it) {
        A_s[baseA + 0 * 4 + 0] = f2tf32(av0.x);
        A_s[baseA + 1 * 4 + 0] = f2tf32(av0.y);
        A_s[baseA + 2 * 4 + 0] = f2tf32(av0.z);
        A_s[baseA + 3 * 4 + 0] = f2tf32(av0.w);
        A_s[baseA + 0 * 4 + 2] = f2tf32(av1.x);
        A_s[baseA + 1 * 4 + 2] = f2tf32(av1.y);
        A_s[baseA + 2 * 4 + 2] = f2tf32(av1.z);
        A_s[baseA + 3 * 4 + 2] = f2tf32(av1.w);
        *(uint4*)(B_s + t * 12)     = bv0;
        *(uint4*)(B_s + t * 12 + 4) = bv1;
        *(uint4*)(B_s + t * 12 + 8) = bv2;
        __syncthreads();
        if (it < 36) {
            av0 = *(const float4*)(arow + (it + 1) * 16);
            av1 = *(const float4*)(arow + (it + 1) * 16 + 4);
            const unsigned* bsrc = g_bfrag + (it + 1) * 3072 + t * 12;
            bv0 = *(const uint4*)(bsrc);
            bv1 = *(const uint4*)(bsrc + 4);
            bv2 = *(const uint4*)(bsrc + 8);
        }
        #pragma unroll
        for (int kc = 0; kc < 2; kc++) {
            unsigned af[2][4];
            #pragma unroll
            for (int i = 0; i < 2; i++) {
                const uint4 v = *(const uint4*)(A_s + ((kc * 8 + wm * 2 + i) * 32 + lane) * 4);
                af[i][0] = v.x; af[i][1] = v.y; af[i][2] = v.z; af[i][3] = v.w;
            }
            #pragma unroll
            for (int j = 0; j < 12; j++) {
                const uint2 b = *(const uint2*)(B_s + ((kc * 24 + wn * 12 + j) * 32 + lane) * 2);
                #pragma unroll
                for (int i = 0; i < 2; i++)
                    MMA_TF32(acc[i][j], af[i][0], af[i][1], af[i][2], af[i][3], b.x, b.y);
            }
        }
        __syncthreads();
    }

    #pragma unroll
    for (int i = 0; i < 2; i++)
        #pragma unroll
        for (int j = 0; j < 12; j++)
            #pragma unroll
            for (int r = 0; r < 4; r++) {
                const int m = wm * 32 + i * 16 + ((r >> 1) << 3) + g;
                const int n = wn * 96 + j * 8 + tg * 2 + (r & 1);
                C1s[m * 196 + n] = fmaxf(acc[i][j][r] + BiasS[n], 0.f);
            }
    __syncthreads();

    {
        const int base = warp * 16;
        float hacc[8][4];
        #pragma unroll
        for (int j = 0; j < 8; j++)
            #pragma unroll
            for (int r = 0; r < 4; r++) hacc[j][r] = 0.f;

        #pragma unroll 4
        for (int k8 = 0; k8 < 16; k8++) {
            const float* cA = C1s + base * 196 + k8 * 8;
            const unsigned a0 = f2tf32(cA[g * 196 + tg]);
            const unsigned a1 = f2tf32(cA[(g + 8) * 196 + tg]);
            const unsigned a2 = f2tf32(cA[g * 196 + tg + 4]);
            const unsigned a3 = f2tf32(cA[(g + 8) * 196 + tg + 4]);
            #pragma unroll
            for (int j = 0; j < 8; j++) {
                const uint2 b = __ldg((const uint2*)g_w2frag + (k8 * 8 + j) * 32 + lane);
                MMA_TF32(hacc[j], a0, a1, a2, a3, b.x, b.y);
            }
        }

        float l0g = 0.f, l1g = 0.f, l0h = 0.f, l1h = 0.f;
        #pragma unroll
        for (int j = 0; j < 8; j++)
            #pragma unroll
            for (int r = 0; r < 4; r++) {
                const int n = j * 8 + tg * 2 + (r & 1);
                const float v = fmaxf(hacc[j][r] + B2s[n], 0.f);
                const float w30 = W3s[n * 2], w31 = W3s[n * 2 + 1];
                if (r < 2) { l0g = fmaf(v, w30, l0g); l1g = fmaf(v, w31, l1g); }
                else       { l0h = fmaf(v, w30, l0h); l1h = fmaf(v, w31, l1h); }
            }
        #pragma unroll
        for (int off = 1; off <= 2; off <<= 1) {
            l0g += __shfl_xor_sync(0xffffffffu, l0g, off);
            l1g += __shfl_xor_sync(0xffffffffu, l1g, off);
            l0h += __shfl_xor_sync(0xffffffffu, l0h, off);
            l1h += __shfl_xor_sync(0xffffffffu, l1h, off);
        }
        if (tg == 0) {
            const float b30 = __ldg(ptb3 + 0), b31 = __ldg(ptb3 + 1);
            {
                const float l0 = l0g + b30, l1 = l1g + b31;
                const float mx = fmaxf(l0, l1);
                const float e0 = expf(l0 - mx), e1 = expf(l1 - mx);
                const float inv = 1.f / (e0 + e1);
                out[(size_t)(m0 + base + g) * 3 + 0] = e0 * inv;
                out[(size_t)(m0 + base + g) * 3 + 1] = e1 * inv;
            }
            {
                const float l0 = l0h + b30, l1 = l1h + b31;
                const float mx = fmaxf(l0, l1);
                const float e0 = expf(l0 - mx), e1 = expf(l1 - mx);
                const float inv = 1.f / (e0 + e1);
                out[(size_t)(m0 + base + g + 8) * 3 + 0] = e0 * inv;
                out[(size_t)(m0 + base + g + 8) * 3 + 1] = e1 * inv;
            }
        }

        for (int i = 0; i < 16; i++) {
            const int ml = base + i;
            const float* c1 = C1s + ml * 196;
            float cc = c1[128 + lane] * CW2s[lane] + c1[160 + lane] * CW2s[lane + 32];
            #pragma unroll
            for (int off = 16; off; off >>= 1)
                cc += __shfl_xor_sync(0xffffffffu, cc, off);
            if (lane == 0)
                out[(size_t)(m0 + ml) * 3 + 2] =
                    1.f / (1.f + expf(-(cc + __ldg(cfb2))));
        }
    }
}

// ---------------------------------------------------------------------------
extern "C" void kernel_launch(void* const* d_in, const int* in_sizes, int n_in,
                              void* d_out, int out_size)
{
    const float* board = (const float*)d_in[0];
    // d_in[1] = target_positions (int64) — mathematically unused
    const float* c1w = (const float*)d_in[2];  const float* c1b = (const float*)d_in[3];
    const float* c2w = (const float*)d_in[4];  const float* c2b = (const float*)d_in[5];
    const float* c3w = (const float*)d_in[6];  const float* c3b = (const float*)d_in[7];
    const float* qp  = (const float*)d_in[8];
    const float* ptw1 = (const float*)d_in[9];  const float* ptb1 = (const float*)d_in[10];
    const float* ptw2 = (const float*)d_in[11]; const float* ptb2 = (const float*)d_in[12];
    const float* ptw3 = (const float*)d_in[13]; const float* ptb3 = (const float*)d_in[14];
    const float* cfw1 = (const float*)d_in[15]; const float* cfb1 = (const float*)d_in[16];
    const float* cfw2 = (const float*)d_in[17]; const float* cfb2 = (const float*)d_in[18];

    int B = in_sizes[0] / 108;
    if (B > BATCH_MAX) B = BATCH_MAX;

    static bool attr_done = false;
    if (!attr_done) {
        cudaFuncSetAttribute(k_conv, cudaFuncAttributeMaxDynamicSharedMemorySize, 4 * 2016 * 8);
        cudaFuncSetAttribute(k_fc1, cudaFuncAttributeMaxDynamicSharedMemorySize, FC1_SMEM);
        attr_done = true;
    }

    const int pairs = (B + 1) / 2;
    k_wt<<<2, 256>>>(c1w);
    k_wb<<<(74 * 24 * 64 + 255) / 256, 256>>>(ptw1, cfw1);
    k_wb2<<<32, 256>>>(ptw2);
    k_wb3<<<72, 256>>>(c3w);
    k_wb2c<<<18, 256>>>(c2w);
    k_conv<<<(pairs + 3) / 4, 128, 4 * 2016 * 8>>>(board, c1b, c2b, c3b, qp, B);
    k_fc1<<<B / 128, 256, FC1_SMEM>>>(ptb1, cfb1,
                                      ptb2, ptw3, ptb3, cfw2, cfb2,
                                      (float*)d_out);
}

// round 10
// speedup vs baseline: 1.8412x; 1.0271x over previous
#include <cuda_runtime.h>
#include <math.h>

#define BATCH_MAX 65536
#define FEAT 584
#define FEAT_PAD 592

typedef unsigned long long u64t;

__device__ float g_feats[(size_t)BATCH_MAX * FEAT_PAD + 16]; // +16 pad for float4 tails

// Weight copies
__device__ float g_w1t[27 * 16];            // [tap][co]
__device__ unsigned g_bfrag[74 * 24 * 64];  // fc1 B, tf32 fragment-major
__device__ unsigned g_w2frag[16 * 8 * 64];  // heads W2, tf32 fragment-major
__device__ unsigned g_w3frag[36 * 8 * 64];  // conv3 W3, tf32 fragment-major
__device__ unsigned g_w2cfrag[18 * 4 * 64]; // conv2 W2, tf32 fragment-major

// ---- packed f32x2 helpers -------------------------------------------------
__device__ __forceinline__ float2 ffma2(float2 a, float2 b, float2 c) {
    u64t ua = *(u64t*)&a, ub = *(u64t*)&b, uc = *(u64t*)&c, ud;
    asm("fma.rn.f32x2 %0, %1, %2, %3;" : "=l"(ud) : "l"(ua), "l"(ub), "l"(uc));
    return *(float2*)&ud;
}
__device__ __forceinline__ float2 bcast2(float w) { return make_float2(w, w); }
__device__ __forceinline__ float2 fmax2(float2 a, float2 b) {
    return make_float2(fmaxf(a.x, b.x), fmaxf(a.y, b.y));
}
__device__ __forceinline__ unsigned f2tf32(float v) {
    unsigned o; asm("cvt.rna.tf32.f32 %0, %1;" : "=r"(o) : "f"(v)); return o;
}
#define MMA_TF32(accp, a0, a1, a2, a3, bx, by)                                \
    asm volatile(                                                             \
        "mma.sync.aligned.m16n8k8.row.col.f32.tf32.tf32.f32 "                 \
        "{%0,%1,%2,%3}, {%4,%5,%6,%7}, {%8,%9}, {%0,%1,%2,%3};"               \
        : "+f"((accp)[0]), "+f"((accp)[1]), "+f"((accp)[2]), "+f"((accp)[3])  \
        : "r"(a0), "r"(a1), "r"(a2), "r"(a3), "r"(bx), "r"(by))

// ---------------------------------------------------------------------------
// Kernel 0: all weight pre-bakes merged (disjoint outputs, idx-guarded).
// ---------------------------------------------------------------------------
__global__ void k_prep(const float* __restrict__ w1,
                       const float* __restrict__ w2,
                       const float* __restrict__ w3,
                       const float* __restrict__ ptw1,
                       const float* __restrict__ cfw1,
                       const float* __restrict__ ptw2)
{
    const int idx = blockIdx.x * 256 + threadIdx.x;

    if (idx < 432) {                       // conv1 transpose
        int co = idx / 27, r = idx - co * 27;
        g_w1t[r * 16 + co] = w1[idx];
    }
    if (idx < 74 * 24 * 64) {              // fc1 B
        const int r = idx & 1;
        const int l = (idx >> 1) & 31;
        const int j = (idx >> 6) % 24;
        const int K8 = idx / (24 * 64);
        const int k = K8 * 8 + r * 4 + (l & 3);
        const int n = j * 8 + (l >> 2);
        float v = 0.f;
        if (k < 584)
            v = (n < 128) ? ptw1[(size_t)k * 128 + n] : cfw1[(size_t)k * 64 + (n - 128)];
        g_bfrag[idx] = f2tf32(v);
    }
    if (idx < 16 * 8 * 64) {               // heads W2
        const int r = idx & 1;
        const int l = (idx >> 1) & 31;
        const int j = (idx >> 6) & 7;
        const int k8 = idx >> 9;
        const int k = k8 * 8 + r * 4 + (l & 3);
        const int n = j * 8 + (l >> 2);
        g_w2frag[idx] = f2tf32(ptw2[(size_t)k * 64 + n]);
    }
    if (idx < 36 * 8 * 64) {               // conv3 W3
        const int r = idx & 1;
        const int l = (idx >> 1) & 31;
        const int j = (idx >> 6) & 7;
        const int k8 = idx >> 9;
        const int k = k8 * 8 + r * 4 + (l & 3);
        const int n = j * 8 + (l >> 2);
        g_w3frag[idx] = f2tf32(w3[(size_t)n * 288 + k]);
    }
    if (idx < 18 * 4 * 64) {               // conv2 W2
        const int r = idx & 1;
        const int l = (idx >> 1) & 31;
        const int j = (idx >> 6) & 3;
        const int k8 = idx >> 8;
        const int k = k8 * 8 + r * 4 + (l & 3);
        const int n = j * 8 + (l >> 2);
        g_w2cfrag[idx] = f2tf32(w2[(size_t)n * 144 + k]);
    }
}

// ---------------------------------------------------------------------------
// conv2 row mapping: r = s*36 + q*4 + sub
// ---------------------------------------------------------------------------
__device__ __forceinline__ int c2_rowbase(int r)
{
    const int s = r / 36, rem = r - 36 * s;
    const int q = rem >> 2, sub = rem & 3;
    const int qy = q / 3, qx = q - 3 * qy;
    const int py = 2 * qy + (sub >> 1);
    const int px = 2 * qx + (sub & 1);
    return (s >> 1) * 4032 + 384 + (s & 1) + 2 * (py * 8 + px);
}

// ---------------------------------------------------------------------------
// conv2 mma tile (fused relu+pool) — unchanged except k8 partial unroll
// ---------------------------------------------------------------------------
__device__ __forceinline__ void conv2_tile(
    float* smf, const int* offk2, const float* b2s,
    int mt, int g, int tg, int lane)
{
    const int r1 = mt * 16 + g, r2 = r1 + 8;
    const int base1 = c2_rowbase(r1), base2 = c2_rowbase(r2);

    float acc[4][4];
    #pragma unroll
    for (int j = 0; j < 4; j++)
        #pragma unroll
        for (int q = 0; q < 4; q++) acc[j][q] = 0.f;

    #pragma unroll 3
    for (int k8 = 0; k8 < 18; k8++) {
        const int oa = offk2[k8 * 8 + tg];
        const int oc = offk2[k8 * 8 + tg + 4];
        const unsigned a0 = f2tf32(smf[base1 + oa]);
        const unsigned a1 = f2tf32(smf[base2 + oa]);
        const unsigned a2 = f2tf32(smf[base1 + oc]);
        const unsigned a3 = f2tf32(smf[base2 + oc]);
        #pragma unroll
        for (int j = 0; j < 4; j++) {
            const uint2 b = __ldg((const uint2*)g_w2cfrag + (k8 * 4 + j) * 32 + lane);
            MMA_TF32(acc[j], a0, a1, a2, a3, b.x, b.y);
        }
    }

    #pragma unroll
    for (int j = 0; j < 4; j++)
        #pragma unroll
        for (int q = 0; q < 4; q++) {
            float v = acc[j][q];
            v = fmaxf(v, __shfl_xor_sync(0xffffffffu, v, 4));
            v = fmaxf(v, __shfl_xor_sync(0xffffffffu, v, 8));
            acc[j][q] = v;
        }
    if ((g & 3) == 0) {
        #pragma unroll
        for (int j = 0; j < 4; j++)
            #pragma unroll
            for (int q = 0; q < 4; q++) {
                const int n = j * 8 + tg * 2 + (q & 1);
                const int r = (q < 2) ? r1 : r2;
                const int gq = r >> 2;
                const int s = gq / 9, qp = gq - 9 * s;
                const int py = qp / 3, px = qp - 3 * py;
                smf[(s >> 1) * 4032 + 2432 + (s & 1)
                    + 2 * (n * 25 + (py + 1) * 5 + (px + 1))]
                    = fmaxf(acc[j][q] + b2s[n], 0.f);
            }
    }
}

// ---------------------------------------------------------------------------
// conv3 mma tile — unchanged except k8 partial unroll
// ---------------------------------------------------------------------------
template<int NN>
__device__ __forceinline__ void conv3_tile(
    float* smf, const int* offk, const float* b3s,
    int mt, int n8lo, int g, int tg, int lane)
{
    const int r1 = mt * 16 + g, r2 = r1 + 8;
    const bool v1 = (r1 < 72), v2 = (r2 < 72);
    int base1 = 0, base2 = 0;
    if (v1) {
        const int s = r1 / 9, p = r1 - 9 * s;
        base1 = (s >> 1) * 4032 + 2432 + (s & 1) + 2 * ((p / 3) * 5 + (p % 3));
    }
    if (v2) {
        const int s = r2 / 9, p = r2 - 9 * s;
        base2 = (s >> 1) * 4032 + 2432 + (s & 1) + 2 * ((p / 3) * 5 + (p % 3));
    }

    float acc[NN][4];
    #pragma unroll
    for (int j = 0; j < NN; j++)
        #pragma unroll
        for (int q = 0; q < 4; q++) acc[j][q] = 0.f;

    #pragma unroll 4
    for (int k8 = 0; k8 < 36; k8++) {
        const int oa = offk[k8 * 8 + tg] * 2;
        const int oc = offk[k8 * 8 + tg + 4] * 2;
        const unsigned a0 = v1 ? f2tf32(smf[base1 + oa]) : 0u;
        const unsigned a1 = v2 ? f2tf32(smf[base2 + oa]) : 0u;
        const unsigned a2 = v1 ? f2tf32(smf[base1 + oc]) : 0u;
        const unsigned a3 = v2 ? f2tf32(smf[base2 + oc]) : 0u;
        #pragma unroll
        for (int j = 0; j < NN; j++) {
            const uint2 b = __ldg((const uint2*)g_w3frag + (k8 * 8 + n8lo + j) * 32 + lane);
            MMA_TF32(acc[j], a0, a1, a2, a3, b.x, b.y);
        }
    }
    #pragma unroll
    for (int j = 0; j < NN; j++)
        #pragma unroll
        for (int q = 0; q < 4; q++) {
            const int n = (n8lo + j) * 8 + tg * 2 + (q & 1);
            const int r = (q < 2) ? r1 : r2;
            if (r < 72)
                smf[(r / 18) * 4032 + 384 + (r % 18) * 65 + n] =
                    fmaxf(acc[j][q] + b3s[n], 0.f);
        }
}

// ---------------------------------------------------------------------------
// Kernel 1: conv pipeline + quantum sim (structure unchanged from round 9)
// ---------------------------------------------------------------------------
__global__ __launch_bounds__(128) void k_conv(
    const float* __restrict__ board,
    const float* __restrict__ b1,
    const float* __restrict__ b2,
    const float* __restrict__ b3,
    const float* __restrict__ qp, int nsamp)
{
    extern __shared__ float2 smc[];
    float* smf = (float*)smc;
    const int tid = threadIdx.x;
    const int warp = tid >> 5, lane = tid & 31;
    const int pidx = blockIdx.x * 4 + warp;
    const int s0 = 2 * pidx;
    const bool active = (s0 < nsamp);
    const bool has2 = (s0 + 1 < nsamp);

    float2* inp = smc + (size_t)warp * 2016;
    float2* h1p = inp + 192;

    for (int i = lane; i < 2016; i += 32) inp[i] = make_float2(0.f, 0.f);
    __syncwarp();

    if (active) {
        const float* bs0 = board + (size_t)s0 * 108;
        const float* bs1 = has2 ? bs0 + 108 : bs0;

        for (int i = lane; i < 108; i += 32) {
            int ci = i / 36, r = i - ci * 36;
            int y = r / 6, x = r - y * 6;
            inp[ci * 64 + (y + 1) * 8 + (x + 1)] = make_float2(bs0[i], bs1[i]);
        }

        if (lane < 16) {
            const int smp = lane >> 3, qb = lane & 7;
            const int sg = s0 + smp;
            if (sg < nsamp) {
                const float* bq = board + (size_t)sg * 108;
                float xv = bq[qb], xn = bq[(qb + 1) & 7];
                float q = 0.f;
                #pragma unroll
                for (int l = 0; l < 3; l++) {
                    float r0 = __ldg(qp + (l * 8 + qb) * 3 + 0);
                    float r1 = __ldg(qp + (l * 8 + qb) * 3 + 1);
                    float r2 = __ldg(qp + (l * 8 + qb) * 3 + 2);
                    q = sinf(r0 * xv) * cosf(r1 * xn) + tanhf(r2 * q);
                }
                g_feats[(size_t)sg * FEAT_PAD + 576 + qb] = q;
                g_feats[(size_t)sg * FEAT_PAD + 584 + qb] = 0.f;
            }
        }
        __syncwarp();

        {   // conv1
            const int co = lane & 15, half = lane >> 4;
            float2 w[27];
            #pragma unroll
            for (int i = 0; i < 27; i++) w[i] = bcast2(__ldg(g_w1t + i * 16 + co));
            const float2 bias = bcast2(__ldg(b1 + co));
            #pragma unroll
            for (int p = 0; p < 18; p++) {
                const int yy = half * 3 + p / 6;
                const int xx = p % 6;
                const int y8 = yy * 8;
                float2 a = bias;
                #pragma unroll
                for (int ci = 0; ci < 3; ci++)
                    #pragma unroll
                    for (int ky = 0; ky < 3; ky++)
                        #pragma unroll
                        for (int kx = 0; kx < 3; kx++)
                            a = ffma2(inp[ci * 64 + y8 + ky * 8 + xx + kx],
                                      w[ci * 9 + ky * 3 + kx], a);
                h1p[co * 64 + y8 + 8 + xx + 1] = fmax2(a, make_float2(0.f, 0.f));
            }
        }
    }
    __syncthreads();

    for (int i = tid; i < 288; i += 128) {
        const int ci = i / 9, tap = i - ci * 9;
        ((int*)smf)[i] = ci * 25 + (tap / 3) * 5 + (tap % 3);
    }
    for (int i = tid; i < 144; i += 128) {
        const int ci = i / 9, tap = i - ci * 9;
        ((int*)(smf + 4032))[i] = 2 * (ci * 64 + (tap / 3) * 8 + (tap % 3));
    }
    if (tid < 64) smf[288 + tid] = __ldg(b3 + tid);
    if (tid < 32) smf[4200 + tid] = __ldg(b2 + tid);
    __syncthreads();

    {   // conv2 via mma
        const int g = lane >> 2, tg = lane & 3;
        const int* offk2 = (const int*)(smf + 4032);
        const float* b2s = smf + 4200;
        conv2_tile(smf, offk2, b2s, warp,      g, tg, lane);
        conv2_tile(smf, offk2, b2s, warp + 4,  g, tg, lane);
        conv2_tile(smf, offk2, b2s, warp + 8,  g, tg, lane);
        conv2_tile(smf, offk2, b2s, warp + 12, g, tg, lane);
        if (warp < 2) conv2_tile(smf, offk2, b2s, 16 + warp, g, tg, lane);
    }
    __syncthreads();

    {   // conv3 via mma
        const int g = lane >> 2, tg = lane & 3;
        const int* offk = (const int*)smf;
        const float* b3s = smf + 288;
        conv3_tile<8>(smf, offk, b3s, warp, 0, g, tg, lane);
        conv3_tile<2>(smf, offk, b3s, 4, 2 * warp, g, tg, lane);
    }
    __syncthreads();

    {   // writeback
        const int s = tid >> 4, li = tid & 15;
        const int sg = blockIdx.x * 8 + s;
        if (sg < nsamp) {
            float* f = g_feats + (size_t)sg * FEAT_PAD;
            for (int i = li; i < 576; i += 16) {
                const int co = i / 9, p = i - 9 * co;
                const int r = s * 9 + p;
                f[i] = smf[(r / 18) * 4032 + 384 + (r % 18) * 65 + co];
            }
        }
    }
}

// ---------------------------------------------------------------------------
// Kernel 2: BM=64, double-buffered tf32 GEMM + tensor-core heads.
// 8 warps: mainloop warp-tile 16(M) x 96(N); heads: warps 0-3 mma (16
// samples each), warps 4-7 confidence head (16 samples each).
// Smem floats: Abuf 2x1024 | Bbuf 2x3072 (= 8192, aliased by C1s 64x196) |
//   BiasS@12544 | W3s@12736 | CW2s@12864 | B2s@12928  => 12992 floats.
// ---------------------------------------------------------------------------
#define FC1_SMEM (12992 * 4)

__global__ __launch_bounds__(256) void k_fc1(
    const float* __restrict__ ptb1, const float* __restrict__ cfb1,
    const float* __restrict__ ptb2,
    const float* __restrict__ ptw3, const float* __restrict__ ptb3,
    const float* __restrict__ cfw2, const float* __restrict__ cfb2,
    float* __restrict__ out)
{
    extern __shared__ float sfc[];
    unsigned* A_s = (unsigned*)sfc;            // 2 x 1024
    unsigned* B_s = (unsigned*)(sfc + 2048);   // 2 x 3072
    float* C1s    = sfc;                       // 12544 (post-GEMM alias)
    float* BiasS  = sfc + 12544;               // 192
    float* W3s    = sfc + 12736;               // 128
    float* CW2s   = sfc + 12864;               // 64
    float* B2s    = sfc + 12928;               // 64

    const int t = threadIdx.x;
    const int m0 = blockIdx.x * 64;
    const int warp = t >> 5, lane = t & 31;
    const int wm = warp >> 1, wn = warp & 1;
    const int g = lane >> 2, tg = lane & 3;

    if (t < 192) BiasS[t] = (t < 128) ? __ldg(ptb1 + t) : __ldg(cfb1 + t - 128);
    if (t < 128) W3s[t] = __ldg(ptw3 + t);
    if (t < 64)  { CW2s[t] = __ldg(cfw2 + t); B2s[t] = __ldg(ptb2 + t); }

    float acc[12][4];
    #pragma unroll
    for (int j = 0; j < 12; j++)
        #pragma unroll
        for (int r = 0; r < 4; r++) acc[j][r] = 0.f;

    // A loader: threads 0..127 cover 64 rows x 2 k8-chunks
    const bool aload = (t < 128);
    const int am = t >> 1;
    const int kcA = t & 1;
    const int rA = am & 15, mtA = (am >> 4) & 3;
    const int baseA = ((kcA * 4 + mtA) * 32 + (rA & 7) * 4) * 4 + (rA >> 3);
    const float* arow = g_feats + (size_t)(m0 + (am & 63)) * FEAT_PAD + kcA * 8;

    float4 av0 = make_float4(0.f, 0.f, 0.f, 0.f);
    float4 av1 = av0;
    if (aload) { av0 = *(const float4*)(arow); av1 = *(const float4*)(arow + 4); }
    uint4 bv0 = *(const uint4*)(g_bfrag + t * 12);
    uint4 bv1 = *(const uint4*)(g_bfrag + t * 12 + 4);
    uint4 bv2 = *(const uint4*)(g_bfrag + t * 12 + 8);

    int p = 0;
    for (int it = 0; it < 37; ++it) {
        unsigned* Ab = A_s + p * 1024;
        unsigned* Bb = B_s + p * 3072;
        if (aload) {
            Ab[baseA + 0 * 4 + 0] = f2tf32(av0.x);
            Ab[baseA + 1 * 4 + 0] = f2tf32(av0.y);
            Ab[baseA + 2 * 4 + 0] = f2tf32(av0.z);
            Ab[baseA + 3 * 4 + 0] = f2tf32(av0.w);
            Ab[baseA + 0 * 4 + 2] = f2tf32(av1.x);
            Ab[baseA + 1 * 4 + 2] = f2tf32(av1.y);
            Ab[baseA + 2 * 4 + 2] = f2tf32(av1.z);
            Ab[baseA + 3 * 4 + 2] = f2tf32(av1.w);
        }
        *(uint4*)(Bb + t * 12)     = bv0;
        *(uint4*)(Bb + t * 12 + 4) = bv1;
        *(uint4*)(Bb + t * 12 + 8) = bv2;
        __syncthreads();
        if (it < 36) {
            if (aload) {
                av0 = *(const float4*)(arow + (it + 1) * 16);
                av1 = *(const float4*)(arow + (it + 1) * 16 + 4);
            }
            const unsigned* bsrc = g_bfrag + (it + 1) * 3072 + t * 12;
            bv0 = *(const uint4*)(bsrc);
            bv1 = *(const uint4*)(bsrc + 4);
            bv2 = *(const uint4*)(bsrc + 8);
        }
        #pragma unroll
        for (int kc = 0; kc < 2; kc++) {
            const uint4 v = *(const uint4*)(Ab + ((kc * 4 + wm) * 32 + lane) * 4);
            #pragma unroll
            for (int j = 0; j < 12; j++) {
                const uint2 b = *(const uint2*)(Bb + ((kc * 24 + wn * 12 + j) * 32 + lane) * 2);
                MMA_TF32(acc[j], v.x, v.y, v.z, v.w, b.x, b.y);
            }
        }
        p ^= 1;
    }
    __syncthreads();   // all mma reads done before C1s aliases A_s/B_s

    // ---- epilogue: bias + relu -> C1s
    #pragma unroll
    for (int j = 0; j < 12; j++)
        #pragma unroll
        for (int r = 0; r < 4; r++) {
            const int m = wm * 16 + ((r >> 1) << 3) + g;
            const int n = wn * 96 + j * 8 + tg * 2 + (r & 1);
            C1s[m * 196 + n] = fmaxf(acc[j][r] + BiasS[n], 0.f);
        }
    __syncthreads();

    if (warp < 4) {
        // ---- heads via mma: warp w -> samples w*16 .. w*16+15
        const int base = warp * 16;
        float hacc[8][4];
        #pragma unroll
        for (int j = 0; j < 8; j++)
            #pragma unroll
            for (int r = 0; r < 4; r++) hacc[j][r] = 0.f;

        #pragma unroll 4
        for (int k8 = 0; k8 < 16; k8++) {
            const float* cA = C1s + base * 196 + k8 * 8;
            const unsigned a0 = f2tf32(cA[g * 196 + tg]);
            const unsigned a1 = f2tf32(cA[(g + 8) * 196 + tg]);
            const unsigned a2 = f2tf32(cA[g * 196 + tg + 4]);
            const unsigned a3 = f2tf32(cA[(g + 8) * 196 + tg + 4]);
            #pragma unroll
            for (int j = 0; j < 8; j++) {
                const uint2 b = __ldg((const uint2*)g_w2frag + (k8 * 8 + j) * 32 + lane);
                MMA_TF32(hacc[j], a0, a1, a2, a3, b.x, b.y);
            }
        }

        float l0g = 0.f, l1g = 0.f, l0h = 0.f, l1h = 0.f;
        #pragma unroll
        for (int j = 0; j < 8; j++)
            #pragma unroll
            for (int r = 0; r < 4; r++) {
                const int n = j * 8 + tg * 2 + (r & 1);
                const float v = fmaxf(hacc[j][r] + B2s[n], 0.f);
                const float w30 = W3s[n * 2], w31 = W3s[n * 2 + 1];
                if (r < 2) { l0g = fmaf(v, w30, l0g); l1g = fmaf(v, w31, l1g); }
                else       { l0h = fmaf(v, w30, l0h); l1h = fmaf(v, w31, l1h); }
            }
        #pragma unroll
        for (int off = 1; off <= 2; off <<= 1) {
            l0g += __shfl_xor_sync(0xffffffffu, l0g, off);
            l1g += __shfl_xor_sync(0xffffffffu, l1g, off);
            l0h += __shfl_xor_sync(0xffffffffu, l0h, off);
            l1h += __shfl_xor_sync(0xffffffffu, l1h, off);
        }
        if (tg == 0) {
            const float b30 = __ldg(ptb3 + 0), b31 = __ldg(ptb3 + 1);
            {
                const float l0 = l0g + b30, l1 = l1g + b31;
                const float mx = fmaxf(l0, l1);
                const float e0 = expf(l0 - mx), e1 = expf(l1 - mx);
                const float inv = 1.f / (e0 + e1);
                out[(size_t)(m0 + base + g) * 3 + 0] = e0 * inv;
                out[(size_t)(m0 + base + g) * 3 + 1] = e1 * inv;
            }
            {
                const float l0 = l0h + b30, l1 = l1h + b31;
                const float mx = fmaxf(l0, l1);
                const float e0 = expf(l0 - mx), e1 = expf(l1 - mx);
                const float inv = 1.f / (e0 + e1);
                out[(size_t)(m0 + base + g + 8) * 3 + 0] = e0 * inv;
                out[(size_t)(m0 + base + g + 8) * 3 + 1] = e1 * inv;
            }
        }
    } else {
        // ---- confidence head: warp w -> samples (w-4)*16 .. +15
        const int base = (warp - 4) * 16;
        for (int i = 0; i < 16; i++) {
            const int ml = base + i;
            const float* c1 = C1s + ml * 196;
            float cc = c1[128 + lane] * CW2s[lane] + c1[160 + lane] * CW2s[lane + 32];
            #pragma unroll
            for (int off = 16; off; off >>= 1)
                cc += __shfl_xor_sync(0xffffffffu, cc, off);
            if (lane == 0)
                out[(size_t)(m0 + ml) * 3 + 2] =
                    1.f / (1.f + expf(-(cc + __ldg(cfb2))));
        }
    }
}

// ---------------------------------------------------------------------------
extern "C" void kernel_launch(void* const* d_in, const int* in_sizes, int n_in,
                              void* d_out, int out_size)
{
    const float* board = (const float*)d_in[0];
    // d_in[1] = target_positions (int64) — mathematically unused
    const float* c1w = (const float*)d_in[2];  const float* c1b = (const float*)d_in[3];
    const float* c2w = (const float*)d_in[4];  const float* c2b = (const float*)d_in[5];
    const float* c3w = (const float*)d_in[6];  const float* c3b = (const float*)d_in[7];
    const float* qp  = (const float*)d_in[8];
    const float* ptw1 = (const float*)d_in[9];  const float* ptb1 = (const float*)d_in[10];
    const float* ptw2 = (const float*)d_in[11]; const float* ptb2 = (const float*)d_in[12];
    const float* ptw3 = (const float*)d_in[13]; const float* ptb3 = (const float*)d_in[14];
    const float* cfw1 = (const float*)d_in[15]; const float* cfb1 = (const float*)d_in[16];
    const float* cfw2 = (const float*)d_in[17]; const float* cfb2 = (const float*)d_in[18];

    int B = in_sizes[0] / 108;
    if (B > BATCH_MAX) B = BATCH_MAX;

    static bool attr_done = false;
    if (!attr_done) {
        cudaFuncSetAttribute(k_conv, cudaFuncAttributeMaxDynamicSharedMemorySize, 4 * 2016 * 8);
        cudaFuncSetAttribute(k_fc1, cudaFuncAttributeMaxDynamicSharedMemorySize, FC1_SMEM);
        attr_done = true;
    }

    const int pairs = (B + 1) / 2;
    k_prep<<<(74 * 24 * 64 + 255) / 256, 256>>>(c1w, c2w, c3w, ptw1, cfw1, ptw2);
    k_conv<<<(pairs + 3) / 4, 128, 4 * 2016 * 8>>>(board, c1b, c2b, c3b, qp, B);
    k_fc1<<<B / 64, 256, FC1_SMEM>>>(ptb1, cfb1,
                                     ptb2, ptw3, ptb3, cfw2, cfb2,
                                     (float*)d_out);
}